// round 4
// baseline (speedup 1.0000x reference)
#include <cuda_runtime.h>
#include <cstdint>

// Problem constants
#define Bv 4
#define Tv 4096
#define Cv 1024
#define Iv 4096
#define Mv (Bv * Tv)          // 16384 tokens
#define NCHUNK 64
#define CLEN (Tv / NCHUNK)    // 64

typedef unsigned long long u64;

// ---------------------------------------------------------------------------
// Scratch (static __device__ globals: allocation-free per harness rules)
// ---------------------------------------------------------------------------
__device__ float g_h   [(size_t)Mv * Cv];
__device__ float g_xk  [(size_t)Mv * Cv];
__device__ float g_xv  [(size_t)Mv * Cv];
__device__ float g_xr  [(size_t)Mv * Cv];
__device__ float g_k   [(size_t)Mv * Cv];
__device__ float g_v   [(size_t)Mv * Cv];
__device__ float g_r   [(size_t)Mv * Cv];
__device__ float g_rwkv[(size_t)Mv * Cv];
__device__ float g_x1  [(size_t)Mv * Cv];
__device__ float g_r2  [(size_t)Mv * Cv];
__device__ float g_k2  [(size_t)Mv * Iv];     // 256 MiB
__device__ float g_sA  [Bv * NCHUNK * Cv];
__device__ float g_sB  [Bv * NCHUNK * Cv];

// ---------------------------------------------------------------------------
// Helpers
// ---------------------------------------------------------------------------
__device__ __forceinline__ float clip20(float x) { return fminf(fmaxf(x, -20.f), 20.f); }
__device__ __forceinline__ float sigm(float x)   { return 1.0f / (1.0f + __expf(-x)); }

__device__ __forceinline__ void ffma2(u64& d, u64 a, u64 b) {
    // packed 2x fp32 FMA (Blackwell-only; ptxas never emits this from C++)
    asm("fma.rn.f32x2 %0, %1, %2, %0;" : "+l"(d) : "l"(a), "l"(b));
}

__device__ __forceinline__ float4 mixf4(float4 m, float4 h, float4 s) {
    float4 o;
    o.x = m.x * h.x + (1.f - m.x) * s.x;
    o.y = m.y * h.y + (1.f - m.y) * s.y;
    o.z = m.z * h.z + (1.f - m.z) * s.z;
    o.w = m.w * h.w + (1.f - m.w) * s.w;
    return o;
}

// ---------------------------------------------------------------------------
// RMSNorm: one block per token row (C=1024, 256 thr x float4)
// ---------------------------------------------------------------------------
__global__ void __launch_bounds__(256) rmsnorm_kernel(const float* __restrict__ x,
                                                      const float* __restrict__ w,
                                                      float* __restrict__ h)
{
    const int row = blockIdx.x;
    const int tid = threadIdx.x;
    const size_t i4 = (size_t)row * (Cv / 4) + tid;
    float4 xv = reinterpret_cast<const float4*>(x)[i4];
    float ss = xv.x * xv.x + xv.y * xv.y + xv.z * xv.z + xv.w * xv.w;
#pragma unroll
    for (int o = 16; o > 0; o >>= 1) ss += __shfl_xor_sync(0xffffffffu, ss, o);
    __shared__ float red[8];
    if ((tid & 31) == 0) red[tid >> 5] = ss;
    __syncthreads();
    float tot = 0.f;
#pragma unroll
    for (int i = 0; i < 8; i++) tot += red[i];
    const float s = rsqrtf(tot * (1.0f / (float)Cv) + 1e-6f);
    float4 wv = reinterpret_cast<const float4*>(w)[tid];
    float4 o4;
    o4.x = xv.x * s * wv.x; o4.y = xv.y * s * wv.y;
    o4.z = xv.z * s * wv.z; o4.w = xv.w * s * wv.w;
    reinterpret_cast<float4*>(h)[i4] = o4;
}

// ---------------------------------------------------------------------------
// Token-shift mixes (shift = h[t-1] within each batch, zeros at t=0)
// ---------------------------------------------------------------------------
__global__ void __launch_bounds__(256) mix3_kernel(const float* __restrict__ h,
    const float* __restrict__ mk, const float* __restrict__ mv, const float* __restrict__ mr,
    float* __restrict__ oxk, float* __restrict__ oxv, float* __restrict__ oxr)
{
    const size_t i = (size_t)blockIdx.x * 256 + threadIdx.x;      // float4 index
    const int c4  = (int)(i & (Cv / 4 - 1));
    const int row = (int)(i >> 8);
    const int t   = row & (Tv - 1);
    float4 hv = reinterpret_cast<const float4*>(h)[i];
    float4 sh = make_float4(0.f, 0.f, 0.f, 0.f);
    if (t != 0) sh = reinterpret_cast<const float4*>(h)[i - (Cv / 4)];
    float4 a = reinterpret_cast<const float4*>(mk)[c4];
    float4 b = reinterpret_cast<const float4*>(mv)[c4];
    float4 d = reinterpret_cast<const float4*>(mr)[c4];
    reinterpret_cast<float4*>(oxk)[i] = mixf4(a, hv, sh);
    reinterpret_cast<float4*>(oxv)[i] = mixf4(b, hv, sh);
    reinterpret_cast<float4*>(oxr)[i] = mixf4(d, hv, sh);
}

__global__ void __launch_bounds__(256) mix2_kernel(const float* __restrict__ h,
    const float* __restrict__ mk, const float* __restrict__ mr,
    float* __restrict__ oxk, float* __restrict__ oxr)
{
    const size_t i = (size_t)blockIdx.x * 256 + threadIdx.x;
    const int c4  = (int)(i & (Cv / 4 - 1));
    const int row = (int)(i >> 8);
    const int t   = row & (Tv - 1);
    float4 hv = reinterpret_cast<const float4*>(h)[i];
    float4 sh = make_float4(0.f, 0.f, 0.f, 0.f);
    if (t != 0) sh = reinterpret_cast<const float4*>(h)[i - (Cv / 4)];
    float4 a = reinterpret_cast<const float4*>(mk)[c4];
    float4 d = reinterpret_cast<const float4*>(mr)[c4];
    reinterpret_cast<float4*>(oxk)[i] = mixf4(a, hv, sh);
    reinterpret_cast<float4*>(oxr)[i] = mixf4(d, hv, sh);
}

// ---------------------------------------------------------------------------
// WKV scan, chunked-parallel (linear recurrence, constant coeff per channel)
// ---------------------------------------------------------------------------
__global__ void __launch_bounds__(1024) wkv_pass1(const float* __restrict__ k,
                                                  const float* __restrict__ v,
                                                  const float* __restrict__ td,
                                                  float* __restrict__ sA,
                                                  float* __restrict__ sB)
{
    const int c = threadIdx.x, chunk = blockIdx.x, b = blockIdx.y;
    const float w  = clip20(-__expf(td[c]));
    const float ew = __expf(w);
    float a = 0.f, bb = 0.f;
    size_t base = ((size_t)(b * Tv) + (size_t)chunk * CLEN) * Cv + c;
    for (int t = 0; t < CLEN; t++) {
        const size_t ix = base + (size_t)t * Cv;
        const float kt = k[ix], vt = v[ix];
        const float ek = __expf(clip20(kt));
        a  = ew * a  + ek * vt;
        bb = ew * bb + ek;
    }
    const int sidx = (b * NCHUNK + chunk) * Cv + c;
    sA[sidx] = a; sB[sidx] = bb;
}

__global__ void __launch_bounds__(1024) wkv_pass2(const float* __restrict__ td,
                                                  float* __restrict__ sA,
                                                  float* __restrict__ sB)
{
    const int c = threadIdx.x, b = blockIdx.x;
    const float w   = clip20(-__expf(td[c]));
    const float ewL = __expf(w * (float)CLEN);   // ew^CLEN
    float Sa = 0.f, Sb = 0.f;
    for (int i = 0; i < NCHUNK; i++) {
        const int idx = (b * NCHUNK + i) * Cv + c;
        const float la = sA[idx], lb = sB[idx];
        sA[idx] = Sa; sB[idx] = Sb;              // exclusive prefix = chunk start state
        Sa = ewL * Sa + la;
        Sb = ewL * Sb + lb;
    }
}

__global__ void __launch_bounds__(1024) wkv_pass3(const float* __restrict__ k,
                                                  const float* __restrict__ v,
                                                  const float* __restrict__ r,
                                                  const float* __restrict__ td,
                                                  const float* __restrict__ tf,
                                                  const float* __restrict__ sA,
                                                  const float* __restrict__ sB,
                                                  float* __restrict__ out)
{
    const int c = threadIdx.x, chunk = blockIdx.x, b = blockIdx.y;
    const float w  = clip20(-__expf(td[c]));
    const float ew = __expf(w);
    const float u  = tf[c];
    const int sidx = (b * NCHUNK + chunk) * Cv + c;
    float a = sA[sidx], bb = sB[sidx];
    size_t base = ((size_t)(b * Tv) + (size_t)chunk * CLEN) * Cv + c;
    for (int t = 0; t < CLEN; t++) {
        const size_t ix = base + (size_t)t * Cv;
        const float kt = k[ix], vt = v[ix];
        const float ekt = __expf(clip20(u + kt));
        const float o = __fdividef(a + ekt * vt, bb + ekt + 1e-8f);
        out[ix] = r[ix] * o;
        const float ek = __expf(clip20(kt));
        a  = ew * a  + ek * vt;
        bb = ew * bb + ek;
    }
}

// ---------------------------------------------------------------------------
// SGEMM: 128x128x16 tiles, 256 threads, 8x8 per thread, fma.rn.f32x2 core.
// A stored DUPLICATED in SMEM so LDS.128 yields broadcast (a,a) pairs for free.
// Register-prefetch double buffering of global tiles.
// ---------------------------------------------------------------------------
enum { EPI_NONE = 0, EPI_SIGMOID = 1, EPI_RELUSQ = 2, EPI_ADD = 3, EPI_MULADD = 4 };

#define BM 128
#define BN 128
#define BKK 16

template<int EPI>
__global__ void __launch_bounds__(256) sgemm_kernel(
    const float* __restrict__ A, const float* __restrict__ Bm, float* __restrict__ Cm,
    int M, int N, int K, const float* __restrict__ E1, const float* __restrict__ E2)
{
    __shared__ __align__(16) float As[BKK][2 * BM + 4];   // duplicated A, row = 260 floats (16B-aligned stride)
    __shared__ __align__(16) float Bs[BKK][BN];

    const int tid = threadIdx.x;
    const int tx  = tid & 15;
    const int ty  = tid >> 4;
    const int am  = tid >> 2;            // A row within half-tile (0..63)
    const int ak  = (tid & 3) << 2;      // A k-offset (0,4,8,12)
    const int kb  = tid >> 5;            // B k-row (0..7)
    const int bnc = (tid & 31) << 2;     // B col (0..124)

    const float* gA = A  + (size_t)(blockIdx.y * BM + am) * K + ak;
    const float* gB = Bm + (size_t)kb * N + blockIdx.x * BN + bnc;

    float4 ra0 = *reinterpret_cast<const float4*>(gA);
    float4 ra1 = *reinterpret_cast<const float4*>(gA + (size_t)64 * K);
    float4 rb0 = *reinterpret_cast<const float4*>(gB);
    float4 rb1 = *reinterpret_cast<const float4*>(gB + (size_t)8 * N);

    u64 acc[8][4];
#pragma unroll
    for (int i = 0; i < 8; i++)
#pragma unroll
        for (int j = 0; j < 4; j++) acc[i][j] = 0ull;

    const int ntiles = K / BKK;
    for (int tno = 0; tno < ntiles; ++tno) {
        // commit prefetched tile to SMEM (A transposed + duplicated)
#pragma unroll
        for (int i = 0; i < 4; i++) {
            const float v0 = (&ra0.x)[i];
            const float v1 = (&ra1.x)[i];
            reinterpret_cast<float2*>(&As[ak + i][0])[am]      = make_float2(v0, v0);
            reinterpret_cast<float2*>(&As[ak + i][0])[am + 64] = make_float2(v1, v1);
        }
        *reinterpret_cast<float4*>(&Bs[kb][bnc])     = rb0;
        *reinterpret_cast<float4*>(&Bs[kb + 8][bnc]) = rb1;
        __syncthreads();

        if (tno + 1 < ntiles) {          // issue next tile's global loads early
            gA += BKK;
            gB += (size_t)BKK * N;
            ra0 = *reinterpret_cast<const float4*>(gA);
            ra1 = *reinterpret_cast<const float4*>(gA + (size_t)64 * K);
            rb0 = *reinterpret_cast<const float4*>(gB);
            rb1 = *reinterpret_cast<const float4*>(gB + (size_t)8 * N);
        }

#pragma unroll
        for (int kk = 0; kk < BKK; ++kk) {
            const ulonglong2 a01 = *reinterpret_cast<const ulonglong2*>(&As[kk][8 * ty]);
            const ulonglong2 a23 = *reinterpret_cast<const ulonglong2*>(&As[kk][8 * ty + 4]);
            const ulonglong2 a45 = *reinterpret_cast<const ulonglong2*>(&As[kk][128 + 8 * ty]);
            const ulonglong2 a67 = *reinterpret_cast<const ulonglong2*>(&As[kk][128 + 8 * ty + 4]);
            const ulonglong2 b01 = *reinterpret_cast<const ulonglong2*>(&Bs[kk][4 * tx]);
            const ulonglong2 b23 = *reinterpret_cast<const ulonglong2*>(&Bs[kk][64 + 4 * tx]);
            u64 ap[8] = {a01.x, a01.y, a23.x, a23.y, a45.x, a45.y, a67.x, a67.y};
            u64 bp[4] = {b01.x, b01.y, b23.x, b23.y};
#pragma unroll
            for (int i = 0; i < 8; i++)
#pragma unroll
                for (int j = 0; j < 4; j++) ffma2(acc[i][j], ap[i], bp[j]);
        }
        __syncthreads();
    }

    // epilogue
    const int rowBase = blockIdx.y * BM;
    const int colBase = blockIdx.x * BN;
#pragma unroll
    for (int i = 0; i < 8; i++) {
        const int r = rowBase + ((i < 4) ? (ty * 4 + i) : (64 + ty * 4 + i - 4));
        const size_t rofs = (size_t)r * N;
#pragma unroll
        for (int g = 0; g < 2; g++) {
            const int c = colBase + (g ? (64 + tx * 4) : (tx * 4));
            union { u64 u; float2 f; } lo, hi;
            lo.u = acc[i][2 * g]; hi.u = acc[i][2 * g + 1];
            float4 vv = make_float4(lo.f.x, lo.f.y, hi.f.x, hi.f.y);
            const size_t idx = rofs + c;
            if (EPI == EPI_SIGMOID) {
                vv.x = sigm(vv.x); vv.y = sigm(vv.y); vv.z = sigm(vv.z); vv.w = sigm(vv.w);
            } else if (EPI == EPI_RELUSQ) {
                const float a0 = fmaxf(vv.x, 0.f), a1 = fmaxf(vv.y, 0.f);
                const float a2 = fmaxf(vv.z, 0.f), a3 = fmaxf(vv.w, 0.f);
                vv = make_float4(a0 * a0, a1 * a1, a2 * a2, a3 * a3);
            } else if (EPI == EPI_ADD) {
                const float4 e = *reinterpret_cast<const float4*>(&E1[idx]);
                vv.x += e.x; vv.y += e.y; vv.z += e.z; vv.w += e.w;
            } else if (EPI == EPI_MULADD) {
                const float4 e1 = *reinterpret_cast<const float4*>(&E1[idx]);
                const float4 e2 = *reinterpret_cast<const float4*>(&E2[idx]);
                vv.x = e1.x + e2.x * vv.x; vv.y = e1.y + e2.y * vv.y;
                vv.z = e1.z + e2.z * vv.z; vv.w = e1.w + e2.w * vv.w;
            }
            *reinterpret_cast<float4*>(&Cm[idx]) = vv;
        }
    }
}

// ---------------------------------------------------------------------------
// Launch
// ---------------------------------------------------------------------------
extern "C" void kernel_launch(void* const* d_in, const int* in_sizes, int n_in,
                              void* d_out, int out_size)
{
    const float* x     = (const float*)d_in[0];
    const float* ln1_w = (const float*)d_in[1];
    const float* ln2_w = (const float*)d_in[2];
    const float* td    = (const float*)d_in[3];
    const float* tf    = (const float*)d_in[4];
    const float* mk    = (const float*)d_in[5];
    const float* mv    = (const float*)d_in[6];
    const float* mr    = (const float*)d_in[7];
    const float* Wk    = (const float*)d_in[8];
    const float* Wv    = (const float*)d_in[9];
    const float* Wr    = (const float*)d_in[10];
    const float* Wo    = (const float*)d_in[11];
    const float* mk2   = (const float*)d_in[12];
    const float* mr2   = (const float*)d_in[13];
    const float* Wk2   = (const float*)d_in[14];
    const float* Wv2   = (const float*)d_in[15];
    const float* Wr2   = (const float*)d_in[16];
    float* out = (float*)d_out;

    float *h, *xk, *xv, *xr, *k, *v, *r, *rwkv, *x1, *r2, *k2, *sA, *sB;
    cudaGetSymbolAddress((void**)&h,    g_h);
    cudaGetSymbolAddress((void**)&xk,   g_xk);
    cudaGetSymbolAddress((void**)&xv,   g_xv);
    cudaGetSymbolAddress((void**)&xr,   g_xr);
    cudaGetSymbolAddress((void**)&k,    g_k);
    cudaGetSymbolAddress((void**)&v,    g_v);
    cudaGetSymbolAddress((void**)&r,    g_r);
    cudaGetSymbolAddress((void**)&rwkv, g_rwkv);
    cudaGetSymbolAddress((void**)&x1,   g_x1);
    cudaGetSymbolAddress((void**)&r2,   g_r2);
    cudaGetSymbolAddress((void**)&k2,   g_k2);
    cudaGetSymbolAddress((void**)&sA,   g_sA);
    cudaGetSymbolAddress((void**)&sB,   g_sB);

    const dim3 gemmC(Cv / BN, Mv / BM);   // (8, 128)
    const dim3 gemmI(Iv / BN, Mv / BM);   // (32, 128)

    // --- time mixing ---
    rmsnorm_kernel<<<Mv, 256>>>(x, ln1_w, h);
    mix3_kernel<<<Mv, 256>>>(h, mk, mv, mr, xk, xv, xr);
    sgemm_kernel<EPI_NONE>   <<<gemmC, 256>>>(xk, Wk, k, Mv, Cv, Cv, nullptr, nullptr);
    sgemm_kernel<EPI_NONE>   <<<gemmC, 256>>>(xv, Wv, v, Mv, Cv, Cv, nullptr, nullptr);
    sgemm_kernel<EPI_SIGMOID><<<gemmC, 256>>>(xr, Wr, r, Mv, Cv, Cv, nullptr, nullptr);
    wkv_pass1<<<dim3(NCHUNK, Bv), Cv>>>(k, v, td, sA, sB);
    wkv_pass2<<<Bv, Cv>>>(td, sA, sB);
    wkv_pass3<<<dim3(NCHUNK, Bv), Cv>>>(k, v, r, td, tf, sA, sB, rwkv);
    sgemm_kernel<EPI_ADD>    <<<gemmC, 256>>>(rwkv, Wo, x1, Mv, Cv, Cv, x, nullptr);

    // --- channel mixing ---
    rmsnorm_kernel<<<Mv, 256>>>(x1, ln2_w, h);
    mix2_kernel<<<Mv, 256>>>(h, mk2, mr2, xk, xr);
    sgemm_kernel<EPI_RELUSQ> <<<gemmI, 256>>>(xk, Wk2, k2, Mv, Iv, Cv, nullptr, nullptr);
    sgemm_kernel<EPI_SIGMOID><<<gemmC, 256>>>(xr, Wr2, r2, Mv, Cv, Cv, nullptr, nullptr);
    sgemm_kernel<EPI_MULADD> <<<gemmC, 256>>>(k2, Wv2, out, Mv, Cv, Iv, x1, r2);
}

// round 6
// speedup vs baseline: 2.1857x; 2.1857x over previous
#include <cuda_runtime.h>
#include <cuda_bf16.h>
#include <cstdint>

#define Bv 4
#define Tv 4096
#define Cv 1024
#define Iv 4096
#define Mv (Bv * Tv)          // 16384 tokens
#define NCHUNK 64
#define CLEN (Tv / NCHUNK)    // 64

typedef unsigned long long u64;
typedef unsigned int u32;

// ===========================================================================
// PTX helpers (sm_80-era only: ldmatrix / mma.sync / cp.async — all legal on
// the harness's bare compute_103 target; tcgen05 is NOT, learned Round 5)
// ===========================================================================
__device__ __forceinline__ u32 smem_to_u32(const void* p) {
    u32 a;
    asm("{ .reg .u64 t; cvta.to.shared.u64 t, %1; cvt.u32.u64 %0, t; }" : "=r"(a) : "l"(p));
    return a;
}
__device__ __forceinline__ void ldsm4(u32* r, u32 addr) {
    asm volatile("ldmatrix.sync.aligned.m8n8.x4.shared.b16 {%0,%1,%2,%3}, [%4];"
                 : "=r"(r[0]), "=r"(r[1]), "=r"(r[2]), "=r"(r[3]) : "r"(addr));
}
__device__ __forceinline__ void mma16816(float* c, const u32* a, const u32* b) {
    asm volatile("mma.sync.aligned.m16n8k16.row.col.f32.bf16.bf16.f32 "
                 "{%0,%1,%2,%3}, {%4,%5,%6,%7}, {%8,%9}, {%0,%1,%2,%3};"
                 : "+f"(c[0]), "+f"(c[1]), "+f"(c[2]), "+f"(c[3])
                 : "r"(a[0]), "r"(a[1]), "r"(a[2]), "r"(a[3]), "r"(b[0]), "r"(b[1]));
}
__device__ __forceinline__ void cpasync16(u32 s, const void* g) {
    asm volatile("cp.async.cg.shared.global [%0], [%1], 16;" :: "r"(s), "l"(g));
}
__device__ __forceinline__ void cpasync_commit() { asm volatile("cp.async.commit_group;" ::: "memory"); }
template<int N> __device__ __forceinline__ void cpasync_wait() {
    asm volatile("cp.async.wait_group %0;" :: "n"(N) : "memory");
}

// ===========================================================================
// Scratch (__device__ globals; allocation-free)
// ===========================================================================
__device__ float g_h  [(size_t)Mv * Cv];
__device__ float g_k  [(size_t)Mv * Cv];
__device__ float g_v  [(size_t)Mv * Cv];
__device__ float g_r  [(size_t)Mv * Cv];
__device__ float g_x1 [(size_t)Mv * Cv];
__device__ float g_r2 [(size_t)Mv * Cv];
__device__ float g_sA [Bv * NCHUNK * Cv];
__device__ float g_sB [Bv * NCHUNK * Cv];

__device__ __nv_bfloat16 a_xk_h[(size_t)Mv * Cv], a_xk_l[(size_t)Mv * Cv];
__device__ __nv_bfloat16 a_xv_h[(size_t)Mv * Cv], a_xv_l[(size_t)Mv * Cv];
__device__ __nv_bfloat16 a_xr_h[(size_t)Mv * Cv], a_xr_l[(size_t)Mv * Cv];
__device__ __nv_bfloat16 a_rw_h[(size_t)Mv * Cv], a_rw_l[(size_t)Mv * Cv];
__device__ __nv_bfloat16 a_k2_h[(size_t)Mv * Iv], a_k2_l[(size_t)Mv * Iv];

// weights transposed to [N,K] K-major bf16 hi/lo
__device__ __nv_bfloat16 w_k_h [Cv * Cv], w_k_l [Cv * Cv];
__device__ __nv_bfloat16 w_v_h [Cv * Cv], w_v_l [Cv * Cv];
__device__ __nv_bfloat16 w_r_h [Cv * Cv], w_r_l [Cv * Cv];
__device__ __nv_bfloat16 w_o_h [Cv * Cv], w_o_l [Cv * Cv];
__device__ __nv_bfloat16 w_r2_h[Cv * Cv], w_r2_l[Cv * Cv];
__device__ __nv_bfloat16 w_k2_h[(size_t)Iv * Cv], w_k2_l[(size_t)Iv * Cv];
__device__ __nv_bfloat16 w_v2_h[(size_t)Cv * Iv], w_v2_l[(size_t)Cv * Iv];

// ===========================================================================
// Numeric helpers
// ===========================================================================
__device__ __forceinline__ float clip20(float x) { return fminf(fmaxf(x, -20.f), 20.f); }
__device__ __forceinline__ float sigm(float x)   { return 1.0f / (1.0f + __expf(-x)); }

__device__ __forceinline__ void split1(float v, uint16_t& h, uint16_t& l) {
    __nv_bfloat16 hb = __float2bfloat16(v);
    float rr = v - __bfloat162float(hb);
    __nv_bfloat16 lb = __float2bfloat16(rr);
    h = *(uint16_t*)&hb; l = *(uint16_t*)&lb;
}
__device__ __forceinline__ void split4st(float4 v, __nv_bfloat16* Hi, __nv_bfloat16* Lo, size_t e) {
    uint16_t h0,l0,h1,l1,h2,l2,h3,l3;
    split1(v.x,h0,l0); split1(v.y,h1,l1); split1(v.z,h2,l2); split1(v.w,h3,l3);
    uint2 hv = make_uint2((u32)h0 | ((u32)h1 << 16), (u32)h2 | ((u32)h3 << 16));
    uint2 lv = make_uint2((u32)l0 | ((u32)l1 << 16), (u32)l2 | ((u32)l3 << 16));
    *reinterpret_cast<uint2*>(Hi + e) = hv;
    *reinterpret_cast<uint2*>(Lo + e) = lv;
}
__device__ __forceinline__ float4 mixf4(float4 m, float4 h, float4 s) {
    float4 o;
    o.x = m.x * h.x + (1.f - m.x) * s.x;
    o.y = m.y * h.y + (1.f - m.y) * s.y;
    o.z = m.z * h.z + (1.f - m.z) * s.z;
    o.w = m.w * h.w + (1.f - m.w) * s.w;
    return o;
}

// ===========================================================================
// RMSNorm (row per block)
// ===========================================================================
__global__ void __launch_bounds__(256) rmsnorm_kernel(const float* __restrict__ x,
                                                      const float* __restrict__ w,
                                                      float* __restrict__ h)
{
    const int row = blockIdx.x, tid = threadIdx.x;
    const size_t i4 = (size_t)row * (Cv / 4) + tid;
    float4 xv = reinterpret_cast<const float4*>(x)[i4];
    float ss = xv.x*xv.x + xv.y*xv.y + xv.z*xv.z + xv.w*xv.w;
#pragma unroll
    for (int o = 16; o > 0; o >>= 1) ss += __shfl_xor_sync(0xffffffffu, ss, o);
    __shared__ float red[8];
    if ((tid & 31) == 0) red[tid >> 5] = ss;
    __syncthreads();
    float tot = 0.f;
#pragma unroll
    for (int i = 0; i < 8; i++) tot += red[i];
    const float s = rsqrtf(tot * (1.0f / (float)Cv) + 1e-6f);
    float4 wv = reinterpret_cast<const float4*>(w)[tid];
    float4 o4 = make_float4(xv.x*s*wv.x, xv.y*s*wv.y, xv.z*s*wv.z, xv.w*s*wv.w);
    reinterpret_cast<float4*>(h)[i4] = o4;
}

// ===========================================================================
// Token-shift mixes with fused bf16 hi/lo split outputs
// ===========================================================================
__global__ void __launch_bounds__(256) mix3s_kernel(const float* __restrict__ h,
    const float* __restrict__ mk, const float* __restrict__ mv, const float* __restrict__ mr,
    __nv_bfloat16* kh, __nv_bfloat16* kl, __nv_bfloat16* vh, __nv_bfloat16* vl,
    __nv_bfloat16* rh, __nv_bfloat16* rl)
{
    const size_t i = (size_t)blockIdx.x * 256 + threadIdx.x;
    const int c4  = (int)(i & (Cv / 4 - 1));
    const int row = (int)(i >> 8);
    const int t   = row & (Tv - 1);
    float4 hv = reinterpret_cast<const float4*>(h)[i];
    float4 sh = make_float4(0.f, 0.f, 0.f, 0.f);
    if (t != 0) sh = reinterpret_cast<const float4*>(h)[i - (Cv / 4)];
    const size_t e = i * 4;
    split4st(mixf4(reinterpret_cast<const float4*>(mk)[c4], hv, sh), kh, kl, e);
    split4st(mixf4(reinterpret_cast<const float4*>(mv)[c4], hv, sh), vh, vl, e);
    split4st(mixf4(reinterpret_cast<const float4*>(mr)[c4], hv, sh), rh, rl, e);
}

__global__ void __launch_bounds__(256) mix2s_kernel(const float* __restrict__ h,
    const float* __restrict__ mk, const float* __restrict__ mr,
    __nv_bfloat16* kh, __nv_bfloat16* kl, __nv_bfloat16* rh, __nv_bfloat16* rl)
{
    const size_t i = (size_t)blockIdx.x * 256 + threadIdx.x;
    const int c4  = (int)(i & (Cv / 4 - 1));
    const int row = (int)(i >> 8);
    const int t   = row & (Tv - 1);
    float4 hv = reinterpret_cast<const float4*>(h)[i];
    float4 sh = make_float4(0.f, 0.f, 0.f, 0.f);
    if (t != 0) sh = reinterpret_cast<const float4*>(h)[i - (Cv / 4)];
    const size_t e = i * 4;
    split4st(mixf4(reinterpret_cast<const float4*>(mk)[c4], hv, sh), kh, kl, e);
    split4st(mixf4(reinterpret_cast<const float4*>(mr)[c4], hv, sh), rh, rl, e);
}

// ===========================================================================
// Weight transpose + split: W[K,N] fp32 -> Whi/Wlo [N,K] bf16
// ===========================================================================
__global__ void __launch_bounds__(256) wsplit_kernel(const float* __restrict__ W,
    __nv_bfloat16* __restrict__ Whi, __nv_bfloat16* __restrict__ Wlo, int K, int N)
{
    __shared__ float t[32][33];
    const int tx = threadIdx.x, ty = threadIdx.y;
    const int n0 = blockIdx.x * 32, k0 = blockIdx.y * 32;
#pragma unroll
    for (int i = ty; i < 32; i += 8)
        t[i][tx] = W[(size_t)(k0 + i) * N + n0 + tx];
    __syncthreads();
#pragma unroll
    for (int i = ty; i < 32; i += 8) {
        const float v = t[tx][i];                       // = W[k0+tx][n0+i]
        uint16_t hh, ll; split1(v, hh, ll);
        const size_t o = (size_t)(n0 + i) * K + k0 + tx;
        Whi[o] = *(__nv_bfloat16*)&hh;
        Wlo[o] = *(__nv_bfloat16*)&ll;
    }
}

// ===========================================================================
// WKV scan (3-pass chunked linear recurrence); pass3 emits r*wkv split bf16
// ===========================================================================
__global__ void __launch_bounds__(1024) wkv_pass1(const float* __restrict__ k,
    const float* __restrict__ v, const float* __restrict__ td,
    float* __restrict__ sA, float* __restrict__ sB)
{
    const int c = threadIdx.x, chunk = blockIdx.x, b = blockIdx.y;
    const float ew = __expf(clip20(-__expf(td[c])));
    float a = 0.f, bb = 0.f;
    size_t base = ((size_t)(b * Tv) + (size_t)chunk * CLEN) * Cv + c;
    for (int t = 0; t < CLEN; t++) {
        const size_t ix = base + (size_t)t * Cv;
        const float kt = k[ix], vt = v[ix];
        const float ek = __expf(clip20(kt));
        a = ew * a + ek * vt;  bb = ew * bb + ek;
    }
    const int sidx = (b * NCHUNK + chunk) * Cv + c;
    sA[sidx] = a; sB[sidx] = bb;
}

__global__ void __launch_bounds__(1024) wkv_pass2(const float* __restrict__ td,
                                                  float* __restrict__ sA, float* __restrict__ sB)
{
    const int c = threadIdx.x, b = blockIdx.x;
    const float w = clip20(-__expf(td[c]));
    const float ewL = __expf(w * (float)CLEN);
    float Sa = 0.f, Sb = 0.f;
    for (int i = 0; i < NCHUNK; i++) {
        const int idx = (b * NCHUNK + i) * Cv + c;
        const float la = sA[idx], lb = sB[idx];
        sA[idx] = Sa; sB[idx] = Sb;
        Sa = ewL * Sa + la;  Sb = ewL * Sb + lb;
    }
}

__global__ void __launch_bounds__(1024) wkv_pass3(const float* __restrict__ k,
    const float* __restrict__ v, const float* __restrict__ r,
    const float* __restrict__ td, const float* __restrict__ tf,
    const float* __restrict__ sA, const float* __restrict__ sB,
    __nv_bfloat16* __restrict__ oh, __nv_bfloat16* __restrict__ ol)
{
    const int c = threadIdx.x, chunk = blockIdx.x, b = blockIdx.y;
    const float ew = __expf(clip20(-__expf(td[c])));
    const float u  = tf[c];
    const int sidx = (b * NCHUNK + chunk) * Cv + c;
    float a = sA[sidx], bb = sB[sidx];
    size_t base = ((size_t)(b * Tv) + (size_t)chunk * CLEN) * Cv + c;
    for (int t = 0; t < CLEN; t++) {
        const size_t ix = base + (size_t)t * Cv;
        const float kt = k[ix], vt = v[ix];
        const float ekt = __expf(clip20(u + kt));
        const float o = r[ix] * __fdividef(a + ekt * vt, bb + ekt + 1e-8f);
        uint16_t hh, ll; split1(o, hh, ll);
        oh[ix] = *(__nv_bfloat16*)&hh;  ol[ix] = *(__nv_bfloat16*)&ll;
        const float ek = __expf(clip20(kt));
        a = ew * a + ek * vt;  bb = ew * bb + ek;
    }
}

// ===========================================================================
// HMMA split-bf16 GEMM: D[M,N] = (Ahi+Alo)[M,K] @ (Bhi+Blo)^T  (B stored [N,K])
// 128x128 tile, Kchunk=64, 3-stage cp.async, mma.sync m16n8k16 fp32 acc.
// 8 warps: warp grid 4(m) x 2(n), warp tile 32x64.
// ===========================================================================
enum { EPI_NONE = 0, EPI_SIGMOID = 1, EPI_ADD = 2, EPI_MULADD = 3, EPI_RELUSQ_SPLIT = 4 };

#define TG_STAGE  65536           // 4 parts x 16KB (Ahi,Alo,Bhi,Blo), 128 rows x 128B
#define TG_STAGES 3
#define TG_SMEM   (TG_STAGES * TG_STAGE)
#define OFF_AH 0
#define OFF_AL 16384
#define OFF_BH 32768
#define OFF_BL 49152

__device__ __forceinline__ u32 swz(u32 o) { return o ^ ((o >> 3) & 0x70); }

template<int EPI>
__global__ void __launch_bounds__(256) hgemm_kernel(
    const __nv_bfloat16* __restrict__ Ahi, const __nv_bfloat16* __restrict__ Alo,
    const __nv_bfloat16* __restrict__ Bhi, const __nv_bfloat16* __restrict__ Blo,
    float* __restrict__ C, __nv_bfloat16* __restrict__ Chi, __nv_bfloat16* __restrict__ Clo,
    int N, int K, const float* __restrict__ E1, const float* __restrict__ E2)
{
    extern __shared__ __align__(1024) char smem[];
    const u32 sbase = smem_to_u32(smem);
    const int tid = threadIdx.x, wid = tid >> 5, lane = tid & 31;

    // ---- cp.async mapping: 2 threads/row, 4x16B each, per 16KB part
    const int lrow = tid >> 1;
    const int segb = (tid & 1) * 64;
    u32 soff[4];
#pragma unroll
    for (int j = 0; j < 4; j++) soff[j] = swz((u32)(lrow * 128 + segb + j * 16));
    const size_t pitch = (size_t)K * 2;
    const char* gAh = (const char*)Ahi + (size_t)(blockIdx.y * 128 + lrow) * pitch + segb;
    const char* gAl = (const char*)Alo + (size_t)(blockIdx.y * 128 + lrow) * pitch + segb;
    const char* gBh = (const char*)Bhi + (size_t)(blockIdx.x * 128 + lrow) * pitch + segb;
    const char* gBl = (const char*)Blo + (size_t)(blockIdx.x * 128 + lrow) * pitch + segb;

    auto ld_chunk = [&](int stage, int c) {
        const u32 sb = sbase + stage * TG_STAGE;
        const size_t go = (size_t)c * 128;   // 64 bf16 = 128 bytes per chunk
#pragma unroll
        for (int j = 0; j < 4; j++) cpasync16(sb + OFF_AH + soff[j], gAh + go + j * 16);
#pragma unroll
        for (int j = 0; j < 4; j++) cpasync16(sb + OFF_AL + soff[j], gAl + go + j * 16);
#pragma unroll
        for (int j = 0; j < 4; j++) cpasync16(sb + OFF_BH + soff[j], gBh + go + j * 16);
#pragma unroll
        for (int j = 0; j < 4; j++) cpasync16(sb + OFF_BL + soff[j], gBl + go + j * 16);
        cpasync_commit();
    };

    // ---- warp tiling / ldmatrix lane addressing
    const int wm = (wid & 3) * 32;       // warp m offset (0..96)
    const int wn = (wid >> 2) * 64;      // warp n offset (0 or 64)
    const int laneA_row = lane & 15;
    const int laneA_kb  = (lane >> 4) * 16;
    const int laneB_row = (lane & 7) | (((lane >> 4) & 1) << 3);
    const int laneB_kb  = ((lane >> 3) & 1) * 16;

    float acc[2][8][4];
#pragma unroll
    for (int i = 0; i < 2; i++)
#pragma unroll
        for (int j = 0; j < 8; j++)
#pragma unroll
            for (int q = 0; q < 4; q++) acc[i][j][q] = 0.f;

    const int nch = K >> 6;
    ld_chunk(0, 0); ld_chunk(1, 1); ld_chunk(2, 2);

    for (int c = 0; c < nch; ++c) {
        if      (c + 2 < nch) cpasync_wait<2>();
        else if (c + 1 < nch) cpasync_wait<1>();
        else                  cpasync_wait<0>();
        __syncthreads();

        const u32 sb = sbase + (c % 3) * TG_STAGE;
#pragma unroll
        for (int ks = 0; ks < 4; ++ks) {
            u32 ah[2][4], al[2][4], bh[4][4], bl[4][4];
            const int kb = ks * 32;
#pragma unroll
            for (int i = 0; i < 2; i++) {
                const u32 o = swz((u32)((wm + 16 * i + laneA_row) * 128 + kb + laneA_kb));
                ldsm4(ah[i], sb + OFF_AH + o);
                ldsm4(al[i], sb + OFF_AL + o);
            }
#pragma unroll
            for (int g = 0; g < 4; g++) {
                const u32 o = swz((u32)((wn + 16 * g + laneB_row) * 128 + kb + laneB_kb));
                ldsm4(bh[g], sb + OFF_BH + o);
                ldsm4(bl[g], sb + OFF_BL + o);
            }
#pragma unroll
            for (int i = 0; i < 2; i++)
#pragma unroll
                for (int j = 0; j < 8; j++) {
                    const u32* Bh = &bh[j >> 1][(j & 1) * 2];
                    const u32* Bl = &bl[j >> 1][(j & 1) * 2];
                    mma16816(acc[i][j], ah[i], Bh);
                    mma16816(acc[i][j], ah[i], Bl);
                    mma16816(acc[i][j], al[i], Bh);
                }
        }
        __syncthreads();
        if (c + 3 < nch) ld_chunk(c % 3, c + 3);
    }

    // ---- epilogue: frag (i,j) -> rows bm+wm+16i+{gid,gid+8}, cols bn+wn+8j+2tg
    const int gid = lane >> 2, tg = lane & 3;
    const int bm = blockIdx.y * 128, bn = blockIdx.x * 128;
#pragma unroll
    for (int i = 0; i < 2; i++) {
        const int r0 = bm + wm + 16 * i + gid;
#pragma unroll
        for (int j = 0; j < 8; j++) {
            const int cc = bn + wn + 8 * j + 2 * tg;
            const size_t idx0 = (size_t)r0 * N + cc;
            const size_t idx1 = idx0 + (size_t)8 * N;
            float v0 = acc[i][j][0], v1 = acc[i][j][1];
            float v2 = acc[i][j][2], v3 = acc[i][j][3];
            if (EPI == EPI_RELUSQ_SPLIT) {
                v0 = fmaxf(v0, 0.f); v0 *= v0;  v1 = fmaxf(v1, 0.f); v1 *= v1;
                v2 = fmaxf(v2, 0.f); v2 *= v2;  v3 = fmaxf(v3, 0.f); v3 *= v3;
                uint16_t h0,l0,h1,l1,h2,l2,h3,l3;
                split1(v0,h0,l0); split1(v1,h1,l1); split1(v2,h2,l2); split1(v3,h3,l3);
                *reinterpret_cast<u32*>(Chi + idx0) = (u32)h0 | ((u32)h1 << 16);
                *reinterpret_cast<u32*>(Clo + idx0) = (u32)l0 | ((u32)l1 << 16);
                *reinterpret_cast<u32*>(Chi + idx1) = (u32)h2 | ((u32)h3 << 16);
                *reinterpret_cast<u32*>(Clo + idx1) = (u32)l2 | ((u32)l3 << 16);
            } else {
                if (EPI == EPI_SIGMOID) {
                    v0 = sigm(v0); v1 = sigm(v1); v2 = sigm(v2); v3 = sigm(v3);
                } else if (EPI == EPI_ADD) {
                    const float2 e0 = *reinterpret_cast<const float2*>(&E1[idx0]);
                    const float2 e1 = *reinterpret_cast<const float2*>(&E1[idx1]);
                    v0 += e0.x; v1 += e0.y; v2 += e1.x; v3 += e1.y;
                } else if (EPI == EPI_MULADD) {
                    const float2 a0 = *reinterpret_cast<const float2*>(&E1[idx0]);
                    const float2 a1 = *reinterpret_cast<const float2*>(&E1[idx1]);
                    const float2 m0 = *reinterpret_cast<const float2*>(&E2[idx0]);
                    const float2 m1 = *reinterpret_cast<const float2*>(&E2[idx1]);
                    v0 = a0.x + m0.x * v0; v1 = a0.y + m0.y * v1;
                    v2 = a1.x + m1.x * v2; v3 = a1.y + m1.y * v3;
                }
                *reinterpret_cast<float2*>(&C[idx0]) = make_float2(v0, v1);
                *reinterpret_cast<float2*>(&C[idx1]) = make_float2(v2, v3);
            }
        }
    }
}

// ===========================================================================
// Launch
// ===========================================================================
extern "C" void kernel_launch(void* const* d_in, const int* in_sizes, int n_in,
                              void* d_out, int out_size)
{
    const float* x     = (const float*)d_in[0];
    const float* ln1_w = (const float*)d_in[1];
    const float* ln2_w = (const float*)d_in[2];
    const float* td    = (const float*)d_in[3];
    const float* tf    = (const float*)d_in[4];
    const float* mk    = (const float*)d_in[5];
    const float* mv    = (const float*)d_in[6];
    const float* mr    = (const float*)d_in[7];
    const float* Wk    = (const float*)d_in[8];
    const float* Wv    = (const float*)d_in[9];
    const float* Wr    = (const float*)d_in[10];
    const float* Wo    = (const float*)d_in[11];
    const float* mk2   = (const float*)d_in[12];
    const float* mr2   = (const float*)d_in[13];
    const float* Wk2   = (const float*)d_in[14];
    const float* Wv2   = (const float*)d_in[15];
    const float* Wr2   = (const float*)d_in[16];
    float* out = (float*)d_out;

#define SYM(p, s) void* p##_; cudaGetSymbolAddress(&p##_, s); auto* p = (decltype(&s[0]))p##_
    SYM(h,   g_h);  SYM(k,   g_k);  SYM(v,   g_v);  SYM(r,   g_r);
    SYM(x1,  g_x1); SYM(r2,  g_r2); SYM(sA,  g_sA); SYM(sB,  g_sB);
    SYM(xkh, a_xk_h); SYM(xkl, a_xk_l); SYM(xvh, a_xv_h); SYM(xvl, a_xv_l);
    SYM(xrh, a_xr_h); SYM(xrl, a_xr_l); SYM(rwh, a_rw_h); SYM(rwl, a_rw_l);
    SYM(k2h, a_k2_h); SYM(k2l, a_k2_l);
    SYM(wkh, w_k_h);  SYM(wkl, w_k_l);  SYM(wvh, w_v_h);  SYM(wvl, w_v_l);
    SYM(wrh, w_r_h);  SYM(wrl, w_r_l);  SYM(woh, w_o_h);  SYM(wol, w_o_l);
    SYM(wr2h, w_r2_h); SYM(wr2l, w_r2_l);
    SYM(wk2h, w_k2_h); SYM(wk2l, w_k2_l);
    SYM(wv2h, w_v2_h); SYM(wv2l, w_v2_l);
#undef SYM

    cudaFuncSetAttribute(hgemm_kernel<EPI_NONE>,         cudaFuncAttributeMaxDynamicSharedMemorySize, TG_SMEM);
    cudaFuncSetAttribute(hgemm_kernel<EPI_SIGMOID>,      cudaFuncAttributeMaxDynamicSharedMemorySize, TG_SMEM);
    cudaFuncSetAttribute(hgemm_kernel<EPI_ADD>,          cudaFuncAttributeMaxDynamicSharedMemorySize, TG_SMEM);
    cudaFuncSetAttribute(hgemm_kernel<EPI_MULADD>,       cudaFuncAttributeMaxDynamicSharedMemorySize, TG_SMEM);
    cudaFuncSetAttribute(hgemm_kernel<EPI_RELUSQ_SPLIT>, cudaFuncAttributeMaxDynamicSharedMemorySize, TG_SMEM);

    const dim3 tb(32, 8);
    // weight transpose + split (W[K,N] -> [N,K] hi/lo)
    wsplit_kernel<<<dim3(Cv/32, Cv/32), tb>>>(Wk,  wkh,  wkl,  Cv, Cv);
    wsplit_kernel<<<dim3(Cv/32, Cv/32), tb>>>(Wv,  wvh,  wvl,  Cv, Cv);
    wsplit_kernel<<<dim3(Cv/32, Cv/32), tb>>>(Wr,  wrh,  wrl,  Cv, Cv);
    wsplit_kernel<<<dim3(Cv/32, Cv/32), tb>>>(Wo,  woh,  wol,  Cv, Cv);
    wsplit_kernel<<<dim3(Cv/32, Cv/32), tb>>>(Wr2, wr2h, wr2l, Cv, Cv);
    wsplit_kernel<<<dim3(Iv/32, Cv/32), tb>>>(Wk2, wk2h, wk2l, Cv, Iv);  // [I,C]
    wsplit_kernel<<<dim3(Cv/32, Iv/32), tb>>>(Wv2, wv2h, wv2l, Iv, Cv);  // [C,I]

    const dim3 gC(Cv / 128, Mv / 128);   // (8, 128)
    const dim3 gI(Iv / 128, Mv / 128);   // (32, 128)

    // --- time mixing ---
    rmsnorm_kernel<<<Mv, 256>>>(x, ln1_w, h);
    mix3s_kernel<<<Mv, 256>>>(h, mk, mv, mr, xkh, xkl, xvh, xvl, xrh, xrl);
    hgemm_kernel<EPI_NONE>   <<<gC, 256, TG_SMEM>>>(xkh, xkl, wkh, wkl, k,  nullptr, nullptr, Cv, Cv, nullptr, nullptr);
    hgemm_kernel<EPI_NONE>   <<<gC, 256, TG_SMEM>>>(xvh, xvl, wvh, wvl, v,  nullptr, nullptr, Cv, Cv, nullptr, nullptr);
    hgemm_kernel<EPI_SIGMOID><<<gC, 256, TG_SMEM>>>(xrh, xrl, wrh, wrl, r,  nullptr, nullptr, Cv, Cv, nullptr, nullptr);
    wkv_pass1<<<dim3(NCHUNK, Bv), Cv>>>(k, v, td, sA, sB);
    wkv_pass2<<<Bv, Cv>>>(td, sA, sB);
    wkv_pass3<<<dim3(NCHUNK, Bv), Cv>>>(k, v, r, td, tf, sA, sB, rwh, rwl);
    hgemm_kernel<EPI_ADD>    <<<gC, 256, TG_SMEM>>>(rwh, rwl, woh, wol, x1, nullptr, nullptr, Cv, Cv, x, nullptr);

    // --- channel mixing ---
    rmsnorm_kernel<<<Mv, 256>>>(x1, ln2_w, h);
    mix2s_kernel<<<Mv, 256>>>(h, mk2, mr2, xkh, xkl, xrh, xrl);
    hgemm_kernel<EPI_RELUSQ_SPLIT><<<gI, 256, TG_SMEM>>>(xkh, xkl, wk2h, wk2l, nullptr, k2h, k2l, Iv, Cv, nullptr, nullptr);
    hgemm_kernel<EPI_SIGMOID>     <<<gC, 256, TG_SMEM>>>(xrh, xrl, wr2h, wr2l, r2, nullptr, nullptr, Cv, Cv, nullptr, nullptr);
    hgemm_kernel<EPI_MULADD>      <<<gC, 256, TG_SMEM>>>(k2h, k2l, wv2h, wv2l, out, nullptr, nullptr, Cv, Iv, x1, r2);
}

// round 7
// speedup vs baseline: 2.5962x; 1.1878x over previous
#include <cuda_runtime.h>
#include <cuda_fp16.h>
#include <cstdint>

#define Bv 4
#define Tv 4096
#define Cv 1024
#define Iv 4096
#define Mv (Bv * Tv)          // 16384 tokens
#define NCHUNK 64
#define CLEN (Tv / NCHUNK)    // 64

typedef unsigned long long u64;
typedef unsigned int u32;

// ===========================================================================
// PTX helpers (sm_80-era only — bare compute_103 target rejects tcgen05)
// ===========================================================================
__device__ __forceinline__ u32 smem_to_u32(const void* p) {
    u32 a;
    asm("{ .reg .u64 t; cvta.to.shared.u64 t, %1; cvt.u32.u64 %0, t; }" : "=r"(a) : "l"(p));
    return a;
}
__device__ __forceinline__ void ldsm4(u32* r, u32 addr) {
    asm volatile("ldmatrix.sync.aligned.m8n8.x4.shared.b16 {%0,%1,%2,%3}, [%4];"
                 : "=r"(r[0]), "=r"(r[1]), "=r"(r[2]), "=r"(r[3]) : "r"(addr));
}
__device__ __forceinline__ void mma16816(float* c, const u32* a, const u32* b) {
    asm volatile("mma.sync.aligned.m16n8k16.row.col.f32.f16.f16.f32 "
                 "{%0,%1,%2,%3}, {%4,%5,%6,%7}, {%8,%9}, {%0,%1,%2,%3};"
                 : "+f"(c[0]), "+f"(c[1]), "+f"(c[2]), "+f"(c[3])
                 : "r"(a[0]), "r"(a[1]), "r"(a[2]), "r"(a[3]), "r"(b[0]), "r"(b[1]));
}
__device__ __forceinline__ void cpasync16(u32 s, const void* g) {
    asm volatile("cp.async.cg.shared.global [%0], [%1], 16;" :: "r"(s), "l"(g));
}
__device__ __forceinline__ void cpasync_commit() { asm volatile("cp.async.commit_group;" ::: "memory"); }
template<int N> __device__ __forceinline__ void cpasync_wait() {
    asm volatile("cp.async.wait_group %0;" :: "n"(N) : "memory");
}

// ===========================================================================
// Scratch (__device__ globals; allocation-free)
// ===========================================================================
__device__ float g_h  [(size_t)Mv * Cv];
__device__ float g_k  [(size_t)Mv * Cv];
__device__ float g_v  [(size_t)Mv * Cv];
__device__ float g_r  [(size_t)Mv * Cv];
__device__ float g_x1 [(size_t)Mv * Cv];
__device__ float g_r2 [(size_t)Mv * Cv];
__device__ float g_sA [Bv * NCHUNK * Cv];
__device__ float g_sB [Bv * NCHUNK * Cv];

__device__ __half a_xk_h[(size_t)Mv * Cv], a_xk_l[(size_t)Mv * Cv];
__device__ __half a_xv_h[(size_t)Mv * Cv], a_xv_l[(size_t)Mv * Cv];
__device__ __half a_xr_h[(size_t)Mv * Cv], a_xr_l[(size_t)Mv * Cv];
__device__ __half a_rw_h[(size_t)Mv * Cv], a_rw_l[(size_t)Mv * Cv];
__device__ __half a_k2_h[(size_t)Mv * Iv], a_k2_l[(size_t)Mv * Iv];

// weights transposed to [N,K] K-major fp16 hi/lo
__device__ __half w_k_h [Cv * Cv], w_k_l [Cv * Cv];
__device__ __half w_v_h [Cv * Cv], w_v_l [Cv * Cv];
__device__ __half w_r_h [Cv * Cv], w_r_l [Cv * Cv];
__device__ __half w_o_h [Cv * Cv], w_o_l [Cv * Cv];
__device__ __half w_r2_h[Cv * Cv], w_r2_l[Cv * Cv];
__device__ __half w_k2_h[(size_t)Iv * Cv], w_k2_l[(size_t)Iv * Cv];
__device__ __half w_v2_h[(size_t)Cv * Iv], w_v2_l[(size_t)Cv * Iv];

// ===========================================================================
// Numeric helpers
// ===========================================================================
__device__ __forceinline__ float clip20(float x) { return fminf(fmaxf(x, -20.f), 20.f); }
__device__ __forceinline__ float sigm(float x)   { return 1.0f / (1.0f + __expf(-x)); }

__device__ __forceinline__ void split1(float v, uint16_t& h, uint16_t& l) {
    __half hb = __float2half_rn(v);
    float rr = v - __half2float(hb);
    __half lb = __float2half_rn(rr);
    h = *(uint16_t*)&hb; l = *(uint16_t*)&lb;
}
__device__ __forceinline__ void split4st(float4 v, __half* Hi, __half* Lo, size_t e) {
    uint16_t h0,l0,h1,l1,h2,l2,h3,l3;
    split1(v.x,h0,l0); split1(v.y,h1,l1); split1(v.z,h2,l2); split1(v.w,h3,l3);
    uint2 hv = make_uint2((u32)h0 | ((u32)h1 << 16), (u32)h2 | ((u32)h3 << 16));
    uint2 lv = make_uint2((u32)l0 | ((u32)l1 << 16), (u32)l2 | ((u32)l3 << 16));
    *reinterpret_cast<uint2*>(Hi + e) = hv;
    *reinterpret_cast<uint2*>(Lo + e) = lv;
}
__device__ __forceinline__ float4 mixf4(float4 m, float4 h, float4 s) {
    float4 o;
    o.x = m.x * h.x + (1.f - m.x) * s.x;
    o.y = m.y * h.y + (1.f - m.y) * s.y;
    o.z = m.z * h.z + (1.f - m.z) * s.z;
    o.w = m.w * h.w + (1.f - m.w) * s.w;
    return o;
}

// ===========================================================================
// RMSNorm (row per block)
// ===========================================================================
__global__ void __launch_bounds__(256) rmsnorm_kernel(const float* __restrict__ x,
                                                      const float* __restrict__ w,
                                                      float* __restrict__ h)
{
    const int row = blockIdx.x, tid = threadIdx.x;
    const size_t i4 = (size_t)row * (Cv / 4) + tid;
    float4 xv = reinterpret_cast<const float4*>(x)[i4];
    float ss = xv.x*xv.x + xv.y*xv.y + xv.z*xv.z + xv.w*xv.w;
#pragma unroll
    for (int o = 16; o > 0; o >>= 1) ss += __shfl_xor_sync(0xffffffffu, ss, o);
    __shared__ float red[8];
    if ((tid & 31) == 0) red[tid >> 5] = ss;
    __syncthreads();
    float tot = 0.f;
#pragma unroll
    for (int i = 0; i < 8; i++) tot += red[i];
    const float s = rsqrtf(tot * (1.0f / (float)Cv) + 1e-6f);
    float4 wv = reinterpret_cast<const float4*>(w)[tid];
    float4 o4 = make_float4(xv.x*s*wv.x, xv.y*s*wv.y, xv.z*s*wv.z, xv.w*s*wv.w);
    reinterpret_cast<float4*>(h)[i4] = o4;
}

// ===========================================================================
// Token-shift mixes with fused fp16 hi/lo split outputs
// ===========================================================================
__global__ void __launch_bounds__(256) mix3s_kernel(const float* __restrict__ h,
    const float* __restrict__ mk, const float* __restrict__ mv, const float* __restrict__ mr,
    __half* kh, __half* kl, __half* vh, __half* vl, __half* rh, __half* rl)
{
    const size_t i = (size_t)blockIdx.x * 256 + threadIdx.x;
    const int c4  = (int)(i & (Cv / 4 - 1));
    const int row = (int)(i >> 8);
    const int t   = row & (Tv - 1);
    float4 hv = reinterpret_cast<const float4*>(h)[i];
    float4 sh = make_float4(0.f, 0.f, 0.f, 0.f);
    if (t != 0) sh = reinterpret_cast<const float4*>(h)[i - (Cv / 4)];
    const size_t e = i * 4;
    split4st(mixf4(reinterpret_cast<const float4*>(mk)[c4], hv, sh), kh, kl, e);
    split4st(mixf4(reinterpret_cast<const float4*>(mv)[c4], hv, sh), vh, vl, e);
    split4st(mixf4(reinterpret_cast<const float4*>(mr)[c4], hv, sh), rh, rl, e);
}

__global__ void __launch_bounds__(256) mix2s_kernel(const float* __restrict__ h,
    const float* __restrict__ mk, const float* __restrict__ mr,
    __half* kh, __half* kl, __half* rh, __half* rl)
{
    const size_t i = (size_t)blockIdx.x * 256 + threadIdx.x;
    const int c4  = (int)(i & (Cv / 4 - 1));
    const int row = (int)(i >> 8);
    const int t   = row & (Tv - 1);
    float4 hv = reinterpret_cast<const float4*>(h)[i];
    float4 sh = make_float4(0.f, 0.f, 0.f, 0.f);
    if (t != 0) sh = reinterpret_cast<const float4*>(h)[i - (Cv / 4)];
    const size_t e = i * 4;
    split4st(mixf4(reinterpret_cast<const float4*>(mk)[c4], hv, sh), kh, kl, e);
    split4st(mixf4(reinterpret_cast<const float4*>(mr)[c4], hv, sh), rh, rl, e);
}

// ===========================================================================
// Weight transpose + split: W[K,N] fp32 -> Whi/Wlo [N,K] fp16
// ===========================================================================
__global__ void __launch_bounds__(256) wsplit_kernel(const float* __restrict__ W,
    __half* __restrict__ Whi, __half* __restrict__ Wlo, int K, int N)
{
    __shared__ float t[32][33];
    const int tx = threadIdx.x, ty = threadIdx.y;
    const int n0 = blockIdx.x * 32, k0 = blockIdx.y * 32;
#pragma unroll
    for (int i = ty; i < 32; i += 8)
        t[i][tx] = W[(size_t)(k0 + i) * N + n0 + tx];
    __syncthreads();
#pragma unroll
    for (int i = ty; i < 32; i += 8) {
        const float v = t[tx][i];                       // = W[k0+tx][n0+i]
        uint16_t hh, ll; split1(v, hh, ll);
        const size_t o = (size_t)(n0 + i) * K + k0 + tx;
        Whi[o] = *(__half*)&hh;
        Wlo[o] = *(__half*)&ll;
    }
}

// ===========================================================================
// WKV scan (3-pass chunked linear recurrence); pass3 emits r*wkv split fp16
// ===========================================================================
__global__ void __launch_bounds__(1024) wkv_pass1(const float* __restrict__ k,
    const float* __restrict__ v, const float* __restrict__ td,
    float* __restrict__ sA, float* __restrict__ sB)
{
    const int c = threadIdx.x, chunk = blockIdx.x, b = blockIdx.y;
    const float ew = __expf(clip20(-__expf(td[c])));
    float a = 0.f, bb = 0.f;
    size_t base = ((size_t)(b * Tv) + (size_t)chunk * CLEN) * Cv + c;
    for (int t = 0; t < CLEN; t++) {
        const size_t ix = base + (size_t)t * Cv;
        const float kt = k[ix], vt = v[ix];
        const float ek = __expf(clip20(kt));
        a = ew * a + ek * vt;  bb = ew * bb + ek;
    }
    const int sidx = (b * NCHUNK + chunk) * Cv + c;
    sA[sidx] = a; sB[sidx] = bb;
}

__global__ void __launch_bounds__(1024) wkv_pass2(const float* __restrict__ td,
                                                  float* __restrict__ sA, float* __restrict__ sB)
{
    const int c = threadIdx.x, b = blockIdx.x;
    const float w = clip20(-__expf(td[c]));
    const float ewL = __expf(w * (float)CLEN);
    float Sa = 0.f, Sb = 0.f;
    for (int i = 0; i < NCHUNK; i++) {
        const int idx = (b * NCHUNK + i) * Cv + c;
        const float la = sA[idx], lb = sB[idx];
        sA[idx] = Sa; sB[idx] = Sb;
        Sa = ewL * Sa + la;  Sb = ewL * Sb + lb;
    }
}

__global__ void __launch_bounds__(1024) wkv_pass3(const float* __restrict__ k,
    const float* __restrict__ v, const float* __restrict__ r,
    const float* __restrict__ td, const float* __restrict__ tf,
    const float* __restrict__ sA, const float* __restrict__ sB,
    __half* __restrict__ oh, __half* __restrict__ ol)
{
    const int c = threadIdx.x, chunk = blockIdx.x, b = blockIdx.y;
    const float ew = __expf(clip20(-__expf(td[c])));
    const float u  = tf[c];
    const int sidx = (b * NCHUNK + chunk) * Cv + c;
    float a = sA[sidx], bb = sB[sidx];
    size_t base = ((size_t)(b * Tv) + (size_t)chunk * CLEN) * Cv + c;
    for (int t = 0; t < CLEN; t++) {
        const size_t ix = base + (size_t)t * Cv;
        const float kt = k[ix], vt = v[ix];
        const float ekt = __expf(clip20(u + kt));
        const float o = r[ix] * __fdividef(a + ekt * vt, bb + ekt + 1e-8f);
        uint16_t hh, ll; split1(o, hh, ll);
        oh[ix] = *(__half*)&hh;  ol[ix] = *(__half*)&ll;
        const float ek = __expf(clip20(kt));
        a = ew * a + ek * vt;  bb = ew * bb + ek;
    }
}

// ===========================================================================
// HMMA split-fp16 GEMM: D = (Ah+Al)@Bh^T [+ Ah@Bl^T if NPROD==3]
// 128x128 tile, Kchunk=64, 3-stage cp.async, ks-level fragment double buffer.
// 8 warps: 4(m) x 2(n), warp tile 32x64.
// ===========================================================================
enum { EPI_NONE = 0, EPI_SIGMOID = 1, EPI_ADD = 2, EPI_MULADD = 3, EPI_RELUSQ_SPLIT = 4 };

#define OFF_AH 0
#define OFF_AL 16384
#define OFF_BH 32768
#define OFF_BL 49152

__device__ __forceinline__ u32 swz(u32 o) { return o ^ ((o >> 3) & 0x70); }

struct Frags { u32 ah[2][4], al[2][4], bh[4][4], bl[4][4]; };

template<int EPI, int NPROD>
__global__ void __launch_bounds__(256) hgemm_kernel(
    const __half* __restrict__ Ahi, const __half* __restrict__ Alo,
    const __half* __restrict__ Bhi, const __half* __restrict__ Blo,
    float* __restrict__ C, __half* __restrict__ Chi, __half* __restrict__ Clo,
    int N, int K, const float* __restrict__ E1, const float* __restrict__ E2)
{
    constexpr int STAGE = (NPROD == 3) ? 65536 : 49152;
    extern __shared__ __align__(1024) char smem[];
    const u32 sbase = smem_to_u32(smem);
    const int tid = threadIdx.x, wid = tid >> 5, lane = tid & 31;

    // ---- cp.async mapping: 2 threads/row, 4x16B each, per 16KB part
    const int lrow = tid >> 1;
    const int segb = (tid & 1) * 64;
    u32 soff[4];
#pragma unroll
    for (int j = 0; j < 4; j++) soff[j] = swz((u32)(lrow * 128 + segb + j * 16));
    const size_t pitch = (size_t)K * 2;
    const char* gAh = (const char*)Ahi + (size_t)(blockIdx.y * 128 + lrow) * pitch + segb;
    const char* gAl = (const char*)Alo + (size_t)(blockIdx.y * 128 + lrow) * pitch + segb;
    const char* gBh = (const char*)Bhi + (size_t)(blockIdx.x * 128 + lrow) * pitch + segb;
    const char* gBl = (const char*)Blo + (size_t)(blockIdx.x * 128 + lrow) * pitch + segb;

    auto ld_chunk = [&](int stage, int c) {
        const u32 sb = sbase + stage * STAGE;
        const size_t go = (size_t)c * 128;   // 64 fp16 = 128 bytes per chunk
#pragma unroll
        for (int j = 0; j < 4; j++) cpasync16(sb + OFF_AH + soff[j], gAh + go + j * 16);
#pragma unroll
        for (int j = 0; j < 4; j++) cpasync16(sb + OFF_AL + soff[j], gAl + go + j * 16);
#pragma unroll
        for (int j = 0; j < 4; j++) cpasync16(sb + OFF_BH + soff[j], gBh + go + j * 16);
        if (NPROD == 3) {
#pragma unroll
            for (int j = 0; j < 4; j++) cpasync16(sb + OFF_BL + soff[j], gBl + go + j * 16);
        }
        cpasync_commit();
    };

    // ---- warp tiling / ldmatrix lane addressing
    const int wm = (wid & 3) * 32;
    const int wn = (wid >> 2) * 64;
    const int laneA_row = lane & 15;
    const int laneA_kb  = (lane >> 4) * 16;
    const int laneB_row = (lane & 7) | (((lane >> 4) & 1) << 3);
    const int laneB_kb  = ((lane >> 3) & 1) * 16;

    auto ld_frags = [&](u32 sb, int ks, Frags& f) {
        const int kb = ks * 32;
#pragma unroll
        for (int i = 0; i < 2; i++) {
            const u32 o = swz((u32)((wm + 16 * i + laneA_row) * 128 + kb + laneA_kb));
            ldsm4(f.ah[i], sb + OFF_AH + o);
            ldsm4(f.al[i], sb + OFF_AL + o);
        }
#pragma unroll
        for (int g = 0; g < 4; g++) {
            const u32 o = swz((u32)((wn + 16 * g + laneB_row) * 128 + kb + laneB_kb));
            ldsm4(f.bh[g], sb + OFF_BH + o);
            if (NPROD == 3) ldsm4(f.bl[g], sb + OFF_BL + o);
        }
    };

    float acc[2][8][4];
#pragma unroll
    for (int i = 0; i < 2; i++)
#pragma unroll
        for (int j = 0; j < 8; j++)
#pragma unroll
            for (int q = 0; q < 4; q++) acc[i][j][q] = 0.f;

    auto mma_step = [&](Frags& f) {
#pragma unroll
        for (int i = 0; i < 2; i++)
#pragma unroll
            for (int j = 0; j < 8; j++) {
                const u32* Bh = &f.bh[j >> 1][(j & 1) * 2];
                mma16816(acc[i][j], f.ah[i], Bh);
                mma16816(acc[i][j], f.al[i], Bh);
                if (NPROD == 3) mma16816(acc[i][j], f.ah[i], &f.bl[j >> 1][(j & 1) * 2]);
            }
    };

    const int nch = K >> 6;
    ld_chunk(0, 0); ld_chunk(1, 1); ld_chunk(2, 2);

    Frags fr[2];
    for (int c = 0; c < nch; ++c) {
        if      (c + 2 < nch) cpasync_wait<2>();
        else if (c + 1 < nch) cpasync_wait<1>();
        else                  cpasync_wait<0>();
        __syncthreads();

        const u32 sb = sbase + (c % 3) * STAGE;
        ld_frags(sb, 0, fr[0]);
#pragma unroll
        for (int ks = 0; ks < 4; ++ks) {
            if (ks < 3) ld_frags(sb, ks + 1, fr[(ks + 1) & 1]);
            mma_step(fr[ks & 1]);
        }
        __syncthreads();
        if (c + 3 < nch) ld_chunk(c % 3, c + 3);
    }

    // ---- epilogue: frag (i,j) -> rows bm+wm+16i+{gid,gid+8}, cols bn+wn+8j+2tg
    const int gid = lane >> 2, tg = lane & 3;
    const int bm = blockIdx.y * 128, bn = blockIdx.x * 128;
#pragma unroll
    for (int i = 0; i < 2; i++) {
        const int r0 = bm + wm + 16 * i + gid;
#pragma unroll
        for (int j = 0; j < 8; j++) {
            const int cc = bn + wn + 8 * j + 2 * tg;
            const size_t idx0 = (size_t)r0 * N + cc;
            const size_t idx1 = idx0 + (size_t)8 * N;
            float v0 = acc[i][j][0], v1 = acc[i][j][1];
            float v2 = acc[i][j][2], v3 = acc[i][j][3];
            if (EPI == EPI_RELUSQ_SPLIT) {
                v0 = fmaxf(v0, 0.f); v0 *= v0;  v1 = fmaxf(v1, 0.f); v1 *= v1;
                v2 = fmaxf(v2, 0.f); v2 *= v2;  v3 = fmaxf(v3, 0.f); v3 *= v3;
                uint16_t h0,l0,h1,l1,h2,l2,h3,l3;
                split1(v0,h0,l0); split1(v1,h1,l1); split1(v2,h2,l2); split1(v3,h3,l3);
                *reinterpret_cast<u32*>(Chi + idx0) = (u32)h0 | ((u32)h1 << 16);
                *reinterpret_cast<u32*>(Clo + idx0) = (u32)l0 | ((u32)l1 << 16);
                *reinterpret_cast<u32*>(Chi + idx1) = (u32)h2 | ((u32)h3 << 16);
                *reinterpret_cast<u32*>(Clo + idx1) = (u32)l2 | ((u32)l3 << 16);
            } else {
                if (EPI == EPI_SIGMOID) {
                    v0 = sigm(v0); v1 = sigm(v1); v2 = sigm(v2); v3 = sigm(v3);
                } else if (EPI == EPI_ADD) {
                    const float2 e0 = *reinterpret_cast<const float2*>(&E1[idx0]);
                    const float2 e1 = *reinterpret_cast<const float2*>(&E1[idx1]);
                    v0 += e0.x; v1 += e0.y; v2 += e1.x; v3 += e1.y;
                } else if (EPI == EPI_MULADD) {
                    const float2 a0 = *reinterpret_cast<const float2*>(&E1[idx0]);
                    const float2 a1 = *reinterpret_cast<const float2*>(&E1[idx1]);
                    const float2 m0 = *reinterpret_cast<const float2*>(&E2[idx0]);
                    const float2 m1 = *reinterpret_cast<const float2*>(&E2[idx1]);
                    v0 = a0.x + m0.x * v0; v1 = a0.y + m0.y * v1;
                    v2 = a1.x + m1.x * v2; v3 = a1.y + m1.y * v3;
                }
                *reinterpret_cast<float2*>(&C[idx0]) = make_float2(v0, v1);
                *reinterpret_cast<float2*>(&C[idx1]) = make_float2(v2, v3);
            }
        }
    }
}

// ===========================================================================
// Launch
// ===========================================================================
extern "C" void kernel_launch(void* const* d_in, const int* in_sizes, int n_in,
                              void* d_out, int out_size)
{
    const float* x     = (const float*)d_in[0];
    const float* ln1_w = (const float*)d_in[1];
    const float* ln2_w = (const float*)d_in[2];
    const float* td    = (const float*)d_in[3];
    const float* tf    = (const float*)d_in[4];
    const float* mk    = (const float*)d_in[5];
    const float* mv    = (const float*)d_in[6];
    const float* mr    = (const float*)d_in[7];
    const float* Wk    = (const float*)d_in[8];
    const float* Wv    = (const float*)d_in[9];
    const float* Wr    = (const float*)d_in[10];
    const float* Wo    = (const float*)d_in[11];
    const float* mk2   = (const float*)d_in[12];
    const float* mr2   = (const float*)d_in[13];
    const float* Wk2   = (const float*)d_in[14];
    const float* Wv2   = (const float*)d_in[15];
    const float* Wr2   = (const float*)d_in[16];
    float* out = (float*)d_out;

#define SYM(p, s) void* p##_; cudaGetSymbolAddress(&p##_, s); auto* p = (decltype(&s[0]))p##_
    SYM(h,   g_h);  SYM(k,   g_k);  SYM(v,   g_v);  SYM(r,   g_r);
    SYM(x1,  g_x1); SYM(r2,  g_r2); SYM(sA,  g_sA); SYM(sB,  g_sB);
    SYM(xkh, a_xk_h); SYM(xkl, a_xk_l); SYM(xvh, a_xv_h); SYM(xvl, a_xv_l);
    SYM(xrh, a_xr_h); SYM(xrl, a_xr_l); SYM(rwh, a_rw_h); SYM(rwl, a_rw_l);
    SYM(k2h, a_k2_h); SYM(k2l, a_k2_l);
    SYM(wkh, w_k_h);  SYM(wkl, w_k_l);  SYM(wvh, w_v_h);  SYM(wvl, w_v_l);
    SYM(wrh, w_r_h);  SYM(wrl, w_r_l);  SYM(woh, w_o_h);  SYM(wol, w_o_l);
    SYM(wr2h, w_r2_h); SYM(wr2l, w_r2_l);
    SYM(wk2h, w_k2_h); SYM(wk2l, w_k2_l);
    SYM(wv2h, w_v2_h); SYM(wv2l, w_v2_l);
#undef SYM

    const int SM3 = 3 * 65536, SM2 = 3 * 49152;
    cudaFuncSetAttribute(hgemm_kernel<EPI_NONE,3>,         cudaFuncAttributeMaxDynamicSharedMemorySize, SM3);
    cudaFuncSetAttribute(hgemm_kernel<EPI_NONE,2>,         cudaFuncAttributeMaxDynamicSharedMemorySize, SM2);
    cudaFuncSetAttribute(hgemm_kernel<EPI_SIGMOID,2>,      cudaFuncAttributeMaxDynamicSharedMemorySize, SM2);
    cudaFuncSetAttribute(hgemm_kernel<EPI_ADD,2>,          cudaFuncAttributeMaxDynamicSharedMemorySize, SM2);
    cudaFuncSetAttribute(hgemm_kernel<EPI_MULADD,2>,       cudaFuncAttributeMaxDynamicSharedMemorySize, SM2);
    cudaFuncSetAttribute(hgemm_kernel<EPI_RELUSQ_SPLIT,3>, cudaFuncAttributeMaxDynamicSharedMemorySize, SM3);

    const dim3 tb(32, 8);
    wsplit_kernel<<<dim3(Cv/32, Cv/32), tb>>>(Wk,  wkh,  wkl,  Cv, Cv);
    wsplit_kernel<<<dim3(Cv/32, Cv/32), tb>>>(Wv,  wvh,  wvl,  Cv, Cv);
    wsplit_kernel<<<dim3(Cv/32, Cv/32), tb>>>(Wr,  wrh,  wrl,  Cv, Cv);
    wsplit_kernel<<<dim3(Cv/32, Cv/32), tb>>>(Wo,  woh,  wol,  Cv, Cv);
    wsplit_kernel<<<dim3(Cv/32, Cv/32), tb>>>(Wr2, wr2h, wr2l, Cv, Cv);
    wsplit_kernel<<<dim3(Iv/32, Cv/32), tb>>>(Wk2, wk2h, wk2l, Cv, Iv);  // [I,C]
    wsplit_kernel<<<dim3(Cv/32, Iv/32), tb>>>(Wv2, wv2h, wv2l, Iv, Cv);  // [C,I]

    const dim3 gC(Cv / 128, Mv / 128);   // (8, 128)
    const dim3 gI(Iv / 128, Mv / 128);   // (32, 128)

    // --- time mixing ---
    rmsnorm_kernel<<<Mv, 256>>>(x, ln1_w, h);
    mix3s_kernel<<<Mv, 256>>>(h, mk, mv, mr, xkh, xkl, xvh, xvl, xrh, xrl);
    hgemm_kernel<EPI_NONE,3>   <<<gC, 256, SM3>>>(xkh, xkl, wkh, wkl, k,  nullptr, nullptr, Cv, Cv, nullptr, nullptr);
    hgemm_kernel<EPI_NONE,2>   <<<gC, 256, SM2>>>(xvh, xvl, wvh, wvl, v,  nullptr, nullptr, Cv, Cv, nullptr, nullptr);
    hgemm_kernel<EPI_SIGMOID,2><<<gC, 256, SM2>>>(xrh, xrl, wrh, wrl, r,  nullptr, nullptr, Cv, Cv, nullptr, nullptr);
    wkv_pass1<<<dim3(NCHUNK, Bv), Cv>>>(k, v, td, sA, sB);
    wkv_pass2<<<Bv, Cv>>>(td, sA, sB);
    wkv_pass3<<<dim3(NCHUNK, Bv), Cv>>>(k, v, r, td, tf, sA, sB, rwh, rwl);
    hgemm_kernel<EPI_ADD,2>    <<<gC, 256, SM2>>>(rwh, rwl, woh, wol, x1, nullptr, nullptr, Cv, Cv, x, nullptr);

    // --- channel mixing ---
    rmsnorm_kernel<<<Mv, 256>>>(x1, ln2_w, h);
    mix2s_kernel<<<Mv, 256>>>(h, mk2, mr2, xkh, xkl, xrh, xrl);
    hgemm_kernel<EPI_RELUSQ_SPLIT,3><<<gI, 256, SM3>>>(xkh, xkl, wk2h, wk2l, nullptr, k2h, k2l, Iv, Cv, nullptr, nullptr);
    hgemm_kernel<EPI_SIGMOID,2>     <<<gC, 256, SM2>>>(xrh, xrl, wr2h, wr2l, r2, nullptr, nullptr, Cv, Cv, nullptr, nullptr);
    hgemm_kernel<EPI_MULADD,2>      <<<gC, 256, SM2>>>(k2h, k2l, wv2h, wv2l, out, nullptr, nullptr, Cv, Iv, x1, r2);
}

// round 8
// speedup vs baseline: 3.9767x; 1.5318x over previous
#include <cuda_runtime.h>
#include <cuda_fp16.h>
#include <cstdint>

#define Bv 4
#define Tv 4096
#define Cv 1024
#define Iv 4096
#define Mv (Bv * Tv)          // 16384 tokens
#define NCHUNK 64
#define CLEN (Tv / NCHUNK)    // 64

typedef unsigned long long u64;
typedef unsigned int u32;

// ===========================================================================
// PTX helpers (sm_80-era only — bare compute_103 target rejects tcgen05)
// ===========================================================================
__device__ __forceinline__ u32 smem_to_u32(const void* p) {
    u32 a;
    asm("{ .reg .u64 t; cvta.to.shared.u64 t, %1; cvt.u32.u64 %0, t; }" : "=r"(a) : "l"(p));
    return a;
}
__device__ __forceinline__ void ldsm4(u32* r, u32 addr) {
    asm volatile("ldmatrix.sync.aligned.m8n8.x4.shared.b16 {%0,%1,%2,%3}, [%4];"
                 : "=r"(r[0]), "=r"(r[1]), "=r"(r[2]), "=r"(r[3]) : "r"(addr));
}
__device__ __forceinline__ void mma16816(float* c, const u32* a, const u32* b) {
    asm volatile("mma.sync.aligned.m16n8k16.row.col.f32.f16.f16.f32 "
                 "{%0,%1,%2,%3}, {%4,%5,%6,%7}, {%8,%9}, {%0,%1,%2,%3};"
                 : "+f"(c[0]), "+f"(c[1]), "+f"(c[2]), "+f"(c[3])
                 : "r"(a[0]), "r"(a[1]), "r"(a[2]), "r"(a[3]), "r"(b[0]), "r"(b[1]));
}
__device__ __forceinline__ void cpasync16(u32 s, const void* g) {
    asm volatile("cp.async.cg.shared.global [%0], [%1], 16;" :: "r"(s), "l"(g));
}
__device__ __forceinline__ void cpasync_commit() { asm volatile("cp.async.commit_group;" ::: "memory"); }
template<int N> __device__ __forceinline__ void cpasync_wait() {
    asm volatile("cp.async.wait_group %0;" :: "n"(N) : "memory");
}

// ===========================================================================
// Scratch (__device__ globals; allocation-free)
// ===========================================================================
__device__ float g_k  [(size_t)Mv * Cv];
__device__ float g_v  [(size_t)Mv * Cv];
__device__ float g_r  [(size_t)Mv * Cv];
__device__ float g_x1 [(size_t)Mv * Cv];
__device__ float g_r2 [(size_t)Mv * Cv];
__device__ float g_sA [Bv * NCHUNK * Cv];
__device__ float g_sB [Bv * NCHUNK * Cv];

__device__ __half a_xk_h[(size_t)Mv * Cv], a_xk_l[(size_t)Mv * Cv];   // k GEMM (3-prod) / k2 GEMM (2-prod A-split)
__device__ __half a_xv_h[(size_t)Mv * Cv];                            // 1-prod
__device__ __half a_xr_h[(size_t)Mv * Cv];                            // 1-prod
__device__ __half a_rw_h[(size_t)Mv * Cv];                            // 1-prod
__device__ __half a_k2_h[(size_t)Mv * Iv];                            // 1-prod (v2 A side)

// weights transposed to [N,K] K-major fp16; lo only kept for Wk (3-prod)
__device__ __half w_k_h [Cv * Cv], w_k_l [Cv * Cv];
__device__ __half w_v_h [Cv * Cv];
__device__ __half w_r_h [Cv * Cv];
__device__ __half w_o_h [Cv * Cv];
__device__ __half w_r2_h[Cv * Cv];
__device__ __half w_k2_h[(size_t)Iv * Cv];
__device__ __half w_v2_h[(size_t)Cv * Iv];

// ===========================================================================
// Numeric helpers
// ===========================================================================
__device__ __forceinline__ float clip20(float x) { return fminf(fmaxf(x, -20.f), 20.f); }
__device__ __forceinline__ float sigm(float x)   { return 1.0f / (1.0f + __expf(-x)); }

__device__ __forceinline__ void split1(float v, uint16_t& h, uint16_t& l) {
    __half hb = __float2half_rn(v);
    float rr = v - __half2float(hb);
    __half lb = __float2half_rn(rr);
    h = *(uint16_t*)&hb; l = *(uint16_t*)&lb;
}
__device__ __forceinline__ u32 pack2h(float a, float b) {
    __half ha = __float2half_rn(a), hb = __float2half_rn(b);
    return (u32)(*(uint16_t*)&ha) | ((u32)(*(uint16_t*)&hb) << 16);
}
__device__ __forceinline__ void split4st(float4 v, __half* Hi, __half* Lo, size_t e) {
    uint16_t h0,l0,h1,l1,h2,l2,h3,l3;
    split1(v.x,h0,l0); split1(v.y,h1,l1); split1(v.z,h2,l2); split1(v.w,h3,l3);
    *reinterpret_cast<uint2*>(Hi + e) =
        make_uint2((u32)h0 | ((u32)h1 << 16), (u32)h2 | ((u32)h3 << 16));
    *reinterpret_cast<uint2*>(Lo + e) =
        make_uint2((u32)l0 | ((u32)l1 << 16), (u32)l2 | ((u32)l3 << 16));
}
__device__ __forceinline__ void round4st(float4 v, __half* Hi, size_t e) {
    *reinterpret_cast<uint2*>(Hi + e) = make_uint2(pack2h(v.x, v.y), pack2h(v.z, v.w));
}
__device__ __forceinline__ float4 mixf4(float4 m, float4 h, float4 s) {
    float4 o;
    o.x = m.x * h.x + (1.f - m.x) * s.x;
    o.y = m.y * h.y + (1.f - m.y) * s.y;
    o.z = m.z * h.z + (1.f - m.z) * s.z;
    o.w = m.w * h.w + (1.f - m.w) * s.w;
    return o;
}

// ===========================================================================
// Fused RMSNorm + token-shift mix (computes norms of rows t and t-1 from x
// directly; eliminates the separate rmsnorm pass and the h buffer)
// ===========================================================================
__device__ __forceinline__ void norm2_reduce(float sc, float sp, float& oc, float& op) {
#pragma unroll
    for (int o = 16; o > 0; o >>= 1) {
        sc += __shfl_xor_sync(0xffffffffu, sc, o);
        sp += __shfl_xor_sync(0xffffffffu, sp, o);
    }
    __shared__ float rc[8], rp[8];
    const int tid = threadIdx.x;
    if ((tid & 31) == 0) { rc[tid >> 5] = sc; rp[tid >> 5] = sp; }
    __syncthreads();
    float tc = 0.f, tp = 0.f;
#pragma unroll
    for (int i = 0; i < 8; i++) { tc += rc[i]; tp += rp[i]; }
    oc = rsqrtf(tc * (1.0f / (float)Cv) + 1e-6f);
    op = rsqrtf(tp * (1.0f / (float)Cv) + 1e-6f);
}

__global__ void __launch_bounds__(256) fusedmix3_kernel(const float* __restrict__ x,
    const float* __restrict__ w,
    const float* __restrict__ mk, const float* __restrict__ mv, const float* __restrict__ mr,
    __half* kh, __half* kl, __half* vh, __half* rh)
{
    const int row = blockIdx.x, tid = threadIdx.x;
    const int t = row & (Tv - 1);
    const size_t i4 = (size_t)row * (Cv / 4) + tid;
    float4 xc = reinterpret_cast<const float4*>(x)[i4];
    float4 xp = make_float4(0.f, 0.f, 0.f, 0.f);
    if (t != 0) xp = reinterpret_cast<const float4*>(x)[i4 - (Cv / 4)];
    float sc, sp;
    norm2_reduce(xc.x*xc.x + xc.y*xc.y + xc.z*xc.z + xc.w*xc.w,
                 xp.x*xp.x + xp.y*xp.y + xp.z*xp.z + xp.w*xp.w, sc, sp);
    float4 wv = reinterpret_cast<const float4*>(w)[tid];
    float4 hv = make_float4(xc.x*sc*wv.x, xc.y*sc*wv.y, xc.z*sc*wv.z, xc.w*sc*wv.w);
    float4 sh = make_float4(xp.x*sp*wv.x, xp.y*sp*wv.y, xp.z*sp*wv.z, xp.w*sp*wv.w);
    const size_t e = i4 * 4;
    split4st(mixf4(reinterpret_cast<const float4*>(mk)[tid], hv, sh), kh, kl, e);
    round4st(mixf4(reinterpret_cast<const float4*>(mv)[tid], hv, sh), vh, e);
    round4st(mixf4(reinterpret_cast<const float4*>(mr)[tid], hv, sh), rh, e);
}

__global__ void __launch_bounds__(256) fusedmix2_kernel(const float* __restrict__ x,
    const float* __restrict__ w,
    const float* __restrict__ mk, const float* __restrict__ mr,
    __half* kh, __half* kl, __half* rh)
{
    const int row = blockIdx.x, tid = threadIdx.x;
    const int t = row & (Tv - 1);
    const size_t i4 = (size_t)row * (Cv / 4) + tid;
    float4 xc = reinterpret_cast<const float4*>(x)[i4];
    float4 xp = make_float4(0.f, 0.f, 0.f, 0.f);
    if (t != 0) xp = reinterpret_cast<const float4*>(x)[i4 - (Cv / 4)];
    float sc, sp;
    norm2_reduce(xc.x*xc.x + xc.y*xc.y + xc.z*xc.z + xc.w*xc.w,
                 xp.x*xp.x + xp.y*xp.y + xp.z*xp.z + xp.w*xp.w, sc, sp);
    float4 wv = reinterpret_cast<const float4*>(w)[tid];
    float4 hv = make_float4(xc.x*sc*wv.x, xc.y*sc*wv.y, xc.z*sc*wv.z, xc.w*sc*wv.w);
    float4 sh = make_float4(xp.x*sp*wv.x, xp.y*sp*wv.y, xp.z*sp*wv.z, xp.w*sp*wv.w);
    const size_t e = i4 * 4;
    split4st(mixf4(reinterpret_cast<const float4*>(mk)[tid], hv, sh), kh, kl, e);
    round4st(mixf4(reinterpret_cast<const float4*>(mr)[tid], hv, sh), rh, e);
}

// ===========================================================================
// Weight transpose (+ optional lo split): W[K,N] fp32 -> [N,K] fp16
// ===========================================================================
template<bool LO>
__global__ void __launch_bounds__(256) wsplit_kernel(const float* __restrict__ W,
    __half* __restrict__ Whi, __half* __restrict__ Wlo, int K, int N)
{
    __shared__ float t[32][33];
    const int tx = threadIdx.x, ty = threadIdx.y;
    const int n0 = blockIdx.x * 32, k0 = blockIdx.y * 32;
#pragma unroll
    for (int i = ty; i < 32; i += 8)
        t[i][tx] = W[(size_t)(k0 + i) * N + n0 + tx];
    __syncthreads();
#pragma unroll
    for (int i = ty; i < 32; i += 8) {
        const float v = t[tx][i];                       // = W[k0+tx][n0+i]
        const size_t o = (size_t)(n0 + i) * K + k0 + tx;
        if (LO) {
            uint16_t hh, ll; split1(v, hh, ll);
            Whi[o] = *(__half*)&hh;  Wlo[o] = *(__half*)&ll;
        } else {
            Whi[o] = __float2half_rn(v);
        }
    }
}

// ===========================================================================
// WKV scan (3-pass chunked linear recurrence); pass3 emits r*wkv fp16 (hi only)
// ===========================================================================
__global__ void __launch_bounds__(1024) wkv_pass1(const float* __restrict__ k,
    const float* __restrict__ v, const float* __restrict__ td,
    float* __restrict__ sA, float* __restrict__ sB)
{
    const int c = threadIdx.x, chunk = blockIdx.x, b = blockIdx.y;
    const float ew = __expf(clip20(-__expf(td[c])));
    float a = 0.f, bb = 0.f;
    size_t base = ((size_t)(b * Tv) + (size_t)chunk * CLEN) * Cv + c;
    for (int t = 0; t < CLEN; t++) {
        const size_t ix = base + (size_t)t * Cv;
        const float kt = k[ix], vt = v[ix];
        const float ek = __expf(clip20(kt));
        a = ew * a + ek * vt;  bb = ew * bb + ek;
    }
    const int sidx = (b * NCHUNK + chunk) * Cv + c;
    sA[sidx] = a; sB[sidx] = bb;
}

__global__ void __launch_bounds__(1024) wkv_pass2(const float* __restrict__ td,
                                                  float* __restrict__ sA, float* __restrict__ sB)
{
    const int c = threadIdx.x, b = blockIdx.x;
    const float w = clip20(-__expf(td[c]));
    const float ewL = __expf(w * (float)CLEN);
    float Sa = 0.f, Sb = 0.f;
    for (int i = 0; i < NCHUNK; i++) {
        const int idx = (b * NCHUNK + i) * Cv + c;
        const float la = sA[idx], lb = sB[idx];
        sA[idx] = Sa; sB[idx] = Sb;
        Sa = ewL * Sa + la;  Sb = ewL * Sb + lb;
    }
}

__global__ void __launch_bounds__(1024) wkv_pass3(const float* __restrict__ k,
    const float* __restrict__ v, const float* __restrict__ r,
    const float* __restrict__ td, const float* __restrict__ tf,
    const float* __restrict__ sA, const float* __restrict__ sB,
    __half* __restrict__ oh)
{
    const int c = threadIdx.x, chunk = blockIdx.x, b = blockIdx.y;
    const float ew = __expf(clip20(-__expf(td[c])));
    const float u  = tf[c];
    const int sidx = (b * NCHUNK + chunk) * Cv + c;
    float a = sA[sidx], bb = sB[sidx];
    size_t base = ((size_t)(b * Tv) + (size_t)chunk * CLEN) * Cv + c;
    for (int t = 0; t < CLEN; t++) {
        const size_t ix = base + (size_t)t * Cv;
        const float kt = k[ix], vt = v[ix];
        const float ekt = __expf(clip20(u + kt));
        const float o = r[ix] * __fdividef(a + ekt * vt, bb + ekt + 1e-8f);
        oh[ix] = __float2half_rn(o);
        const float ek = __expf(clip20(kt));
        a = ew * a + ek * vt;  bb = ew * bb + ek;
    }
}

// ===========================================================================
// HMMA split-fp16 GEMM.
//   NPROD=1: D = Ah@Bh^T
//   NPROD=2: D = (Ah+Al)@Bh^T
//   NPROD=3: D = (Ah+Al)@Bh^T + Ah@Bl^T
// 128x128 tile, Kchunk=64, 3-stage cp.async, fragment double buffer.
// 8 warps: 4(m) x 2(n), warp tile 32x64.
// ===========================================================================
enum { EPI_NONE = 0, EPI_SIGMOID = 1, EPI_ADD = 2, EPI_MULADD = 3, EPI_RELUSQ_H = 4 };

__device__ __forceinline__ u32 swz(u32 o) { return o ^ ((o >> 3) & 0x70); }

struct Frags { u32 ah[2][4], al[2][4], bh[4][4], bl[4][4]; };

template<int EPI, int NPROD>
__global__ void __launch_bounds__(256) hgemm_kernel(
    const __half* __restrict__ Ahi, const __half* __restrict__ Alo,
    const __half* __restrict__ Bhi, const __half* __restrict__ Blo,
    float* __restrict__ C, __half* __restrict__ Chi,
    int N, int K, const float* __restrict__ E1, const float* __restrict__ E2)
{
    constexpr int STAGE  = 16384 * (NPROD + 1);
    constexpr int OFF_AH = 0;
    constexpr int OFF_AL = 16384;                            // valid when NPROD>=2
    constexpr int OFF_BH = (NPROD >= 2) ? 32768 : 16384;
    constexpr int OFF_BL = 49152;                            // valid when NPROD==3
    extern __shared__ __align__(1024) char smem[];
    const u32 sbase = smem_to_u32(smem);
    const int tid = threadIdx.x, wid = tid >> 5, lane = tid & 31;

    // ---- cp.async mapping: 2 threads/row, 4x16B each, per 16KB part
    const int lrow = tid >> 1;
    const int segb = (tid & 1) * 64;
    u32 soff[4];
#pragma unroll
    for (int j = 0; j < 4; j++) soff[j] = swz((u32)(lrow * 128 + segb + j * 16));
    const size_t pitch = (size_t)K * 2;
    const char* gAh = (const char*)Ahi + (size_t)(blockIdx.y * 128 + lrow) * pitch + segb;
    const char* gAl = (NPROD >= 2) ? (const char*)Alo + (size_t)(blockIdx.y * 128 + lrow) * pitch + segb : nullptr;
    const char* gBh = (const char*)Bhi + (size_t)(blockIdx.x * 128 + lrow) * pitch + segb;
    const char* gBl = (NPROD == 3) ? (const char*)Blo + (size_t)(blockIdx.x * 128 + lrow) * pitch + segb : nullptr;

    auto ld_chunk = [&](int stage, int c) {
        const u32 sb = sbase + stage * STAGE;
        const size_t go = (size_t)c * 128;   // 64 fp16 = 128 bytes per chunk
#pragma unroll
        for (int j = 0; j < 4; j++) cpasync16(sb + OFF_AH + soff[j], gAh + go + j * 16);
        if (NPROD >= 2) {
#pragma unroll
            for (int j = 0; j < 4; j++) cpasync16(sb + OFF_AL + soff[j], gAl + go + j * 16);
        }
#pragma unroll
        for (int j = 0; j < 4; j++) cpasync16(sb + OFF_BH + soff[j], gBh + go + j * 16);
        if (NPROD == 3) {
#pragma unroll
            for (int j = 0; j < 4; j++) cpasync16(sb + OFF_BL + soff[j], gBl + go + j * 16);
        }
        cpasync_commit();
    };

    // ---- warp tiling / ldmatrix lane addressing
    const int wm = (wid & 3) * 32;
    const int wn = (wid >> 2) * 64;
    const int laneA_row = lane & 15;
    const int laneA_kb  = (lane >> 4) * 16;
    const int laneB_row = (lane & 7) | (((lane >> 4) & 1) << 3);
    const int laneB_kb  = ((lane >> 3) & 1) * 16;

    auto ld_frags = [&](u32 sb, int ks, Frags& f) {
        const int kb = ks * 32;
#pragma unroll
        for (int i = 0; i < 2; i++) {
            const u32 o = swz((u32)((wm + 16 * i + laneA_row) * 128 + kb + laneA_kb));
            ldsm4(f.ah[i], sb + OFF_AH + o);
            if (NPROD >= 2) ldsm4(f.al[i], sb + OFF_AL + o);
        }
#pragma unroll
        for (int g = 0; g < 4; g++) {
            const u32 o = swz((u32)((wn + 16 * g + laneB_row) * 128 + kb + laneB_kb));
            ldsm4(f.bh[g], sb + OFF_BH + o);
            if (NPROD == 3) ldsm4(f.bl[g], sb + OFF_BL + o);
        }
    };

    float acc[2][8][4];
#pragma unroll
    for (int i = 0; i < 2; i++)
#pragma unroll
        for (int j = 0; j < 8; j++)
#pragma unroll
            for (int q = 0; q < 4; q++) acc[i][j][q] = 0.f;

    auto mma_step = [&](Frags& f) {
#pragma unroll
        for (int i = 0; i < 2; i++)
#pragma unroll
            for (int j = 0; j < 8; j++) {
                const u32* Bh = &f.bh[j >> 1][(j & 1) * 2];
                mma16816(acc[i][j], f.ah[i], Bh);
                if (NPROD >= 2) mma16816(acc[i][j], f.al[i], Bh);
                if (NPROD == 3) mma16816(acc[i][j], f.ah[i], &f.bl[j >> 1][(j & 1) * 2]);
            }
    };

    const int nch = K >> 6;
    ld_chunk(0, 0); ld_chunk(1, 1); ld_chunk(2, 2);

    Frags fr[2];
    for (int c = 0; c < nch; ++c) {
        if      (c + 2 < nch) cpasync_wait<2>();
        else if (c + 1 < nch) cpasync_wait<1>();
        else                  cpasync_wait<0>();
        __syncthreads();

        const u32 sb = sbase + (c % 3) * STAGE;
        ld_frags(sb, 0, fr[0]);
#pragma unroll
        for (int ks = 0; ks < 4; ++ks) {
            if (ks < 3) ld_frags(sb, ks + 1, fr[(ks + 1) & 1]);
            mma_step(fr[ks & 1]);
        }
        __syncthreads();
        if (c + 3 < nch) ld_chunk(c % 3, c + 3);
    }

    // ---- epilogue: frag (i,j) -> rows bm+wm+16i+{gid,gid+8}, cols bn+wn+8j+2tg
    const int gid = lane >> 2, tg = lane & 3;
    const int bm = blockIdx.y * 128, bn = blockIdx.x * 128;
#pragma unroll
    for (int i = 0; i < 2; i++) {
        const int r0 = bm + wm + 16 * i + gid;
#pragma unroll
        for (int j = 0; j < 8; j++) {
            const int cc = bn + wn + 8 * j + 2 * tg;
            const size_t idx0 = (size_t)r0 * N + cc;
            const size_t idx1 = idx0 + (size_t)8 * N;
            float v0 = acc[i][j][0], v1 = acc[i][j][1];
            float v2 = acc[i][j][2], v3 = acc[i][j][3];
            if (EPI == EPI_RELUSQ_H) {
                v0 = fmaxf(v0, 0.f); v0 *= v0;  v1 = fmaxf(v1, 0.f); v1 *= v1;
                v2 = fmaxf(v2, 0.f); v2 *= v2;  v3 = fmaxf(v3, 0.f); v3 *= v3;
                *reinterpret_cast<u32*>(Chi + idx0) = pack2h(v0, v1);
                *reinterpret_cast<u32*>(Chi + idx1) = pack2h(v2, v3);
            } else {
                if (EPI == EPI_SIGMOID) {
                    v0 = sigm(v0); v1 = sigm(v1); v2 = sigm(v2); v3 = sigm(v3);
                } else if (EPI == EPI_ADD) {
                    const float2 e0 = *reinterpret_cast<const float2*>(&E1[idx0]);
                    const float2 e1 = *reinterpret_cast<const float2*>(&E1[idx1]);
                    v0 += e0.x; v1 += e0.y; v2 += e1.x; v3 += e1.y;
                } else if (EPI == EPI_MULADD) {
                    const float2 a0 = *reinterpret_cast<const float2*>(&E1[idx0]);
                    const float2 a1 = *reinterpret_cast<const float2*>(&E1[idx1]);
                    const float2 m0 = *reinterpret_cast<const float2*>(&E2[idx0]);
                    const float2 m1 = *reinterpret_cast<const float2*>(&E2[idx1]);
                    v0 = a0.x + m0.x * v0; v1 = a0.y + m0.y * v1;
                    v2 = a1.x + m1.x * v2; v3 = a1.y + m1.y * v3;
                }
                *reinterpret_cast<float2*>(&C[idx0]) = make_float2(v0, v1);
                *reinterpret_cast<float2*>(&C[idx1]) = make_float2(v2, v3);
            }
        }
    }
}

// ===========================================================================
// Launch
// ===========================================================================
extern "C" void kernel_launch(void* const* d_in, const int* in_sizes, int n_in,
                              void* d_out, int out_size)
{
    const float* x     = (const float*)d_in[0];
    const float* ln1_w = (const float*)d_in[1];
    const float* ln2_w = (const float*)d_in[2];
    const float* td    = (const float*)d_in[3];
    const float* tf    = (const float*)d_in[4];
    const float* mk    = (const float*)d_in[5];
    const float* mv    = (const float*)d_in[6];
    const float* mr    = (const float*)d_in[7];
    const float* Wk    = (const float*)d_in[8];
    const float* Wv    = (const float*)d_in[9];
    const float* Wr    = (const float*)d_in[10];
    const float* Wo    = (const float*)d_in[11];
    const float* mk2   = (const float*)d_in[12];
    const float* mr2   = (const float*)d_in[13];
    const float* Wk2   = (const float*)d_in[14];
    const float* Wv2   = (const float*)d_in[15];
    const float* Wr2   = (const float*)d_in[16];
    float* out = (float*)d_out;

#define SYM(p, s) void* p##_; cudaGetSymbolAddress(&p##_, s); auto* p = (decltype(&s[0]))p##_
    SYM(k,   g_k);  SYM(v,   g_v);  SYM(r,   g_r);
    SYM(x1,  g_x1); SYM(r2,  g_r2); SYM(sA,  g_sA); SYM(sB,  g_sB);
    SYM(xkh, a_xk_h); SYM(xkl, a_xk_l); SYM(xvh, a_xv_h); SYM(xrh, a_xr_h);
    SYM(rwh, a_rw_h); SYM(k2h, a_k2_h);
    SYM(wkh, w_k_h);  SYM(wkl, w_k_l);
    SYM(wvh, w_v_h);  SYM(wrh, w_r_h);  SYM(woh, w_o_h);
    SYM(wr2h, w_r2_h); SYM(wk2h, w_k2_h); SYM(wv2h, w_v2_h);
#undef SYM

    const int SM3 = 3 * 65536, SM2 = 3 * 49152, SM1 = 3 * 32768;
    cudaFuncSetAttribute(hgemm_kernel<EPI_NONE,3>,     cudaFuncAttributeMaxDynamicSharedMemorySize, SM3);
    cudaFuncSetAttribute(hgemm_kernel<EPI_NONE,1>,     cudaFuncAttributeMaxDynamicSharedMemorySize, SM1);
    cudaFuncSetAttribute(hgemm_kernel<EPI_SIGMOID,1>,  cudaFuncAttributeMaxDynamicSharedMemorySize, SM1);
    cudaFuncSetAttribute(hgemm_kernel<EPI_ADD,1>,      cudaFuncAttributeMaxDynamicSharedMemorySize, SM1);
    cudaFuncSetAttribute(hgemm_kernel<EPI_MULADD,1>,   cudaFuncAttributeMaxDynamicSharedMemorySize, SM1);
    cudaFuncSetAttribute(hgemm_kernel<EPI_RELUSQ_H,2>, cudaFuncAttributeMaxDynamicSharedMemorySize, SM2);

    const dim3 tb(32, 8);
    wsplit_kernel<true> <<<dim3(Cv/32, Cv/32), tb>>>(Wk,  wkh,  wkl,   Cv, Cv);
    wsplit_kernel<false><<<dim3(Cv/32, Cv/32), tb>>>(Wv,  wvh,  nullptr, Cv, Cv);
    wsplit_kernel<false><<<dim3(Cv/32, Cv/32), tb>>>(Wr,  wrh,  nullptr, Cv, Cv);
    wsplit_kernel<false><<<dim3(Cv/32, Cv/32), tb>>>(Wo,  woh,  nullptr, Cv, Cv);
    wsplit_kernel<false><<<dim3(Cv/32, Cv/32), tb>>>(Wr2, wr2h, nullptr, Cv, Cv);
    wsplit_kernel<false><<<dim3(Iv/32, Cv/32), tb>>>(Wk2, wk2h, nullptr, Cv, Iv);  // [I,C]
    wsplit_kernel<false><<<dim3(Cv/32, Iv/32), tb>>>(Wv2, wv2h, nullptr, Iv, Cv);  // [C,I]

    const dim3 gC(Cv / 128, Mv / 128);   // (8, 128)
    const dim3 gI(Iv / 128, Mv / 128);   // (32, 128)

    // --- time mixing ---
    fusedmix3_kernel<<<Mv, 256>>>(x, ln1_w, mk, mv, mr, xkh, xkl, xvh, xrh);
    hgemm_kernel<EPI_NONE,3>   <<<gC, 256, SM3>>>(xkh, xkl, wkh, wkl, k, nullptr, Cv, Cv, nullptr, nullptr);
    hgemm_kernel<EPI_NONE,1>   <<<gC, 256, SM1>>>(xvh, nullptr, wvh, nullptr, v, nullptr, Cv, Cv, nullptr, nullptr);
    hgemm_kernel<EPI_SIGMOID,1><<<gC, 256, SM1>>>(xrh, nullptr, wrh, nullptr, r, nullptr, Cv, Cv, nullptr, nullptr);
    wkv_pass1<<<dim3(NCHUNK, Bv), Cv>>>(k, v, td, sA, sB);
    wkv_pass2<<<Bv, Cv>>>(td, sA, sB);
    wkv_pass3<<<dim3(NCHUNK, Bv), Cv>>>(k, v, r, td, tf, sA, sB, rwh);
    hgemm_kernel<EPI_ADD,1>    <<<gC, 256, SM1>>>(rwh, nullptr, woh, nullptr, x1, nullptr, Cv, Cv, x, nullptr);

    // --- channel mixing ---
    fusedmix2_kernel<<<Mv, 256>>>(x1, ln2_w, mk2, mr2, xkh, xkl, xrh);
    hgemm_kernel<EPI_RELUSQ_H,2><<<gI, 256, SM2>>>(xkh, xkl, wk2h, nullptr, nullptr, k2h, Iv, Cv, nullptr, nullptr);
    hgemm_kernel<EPI_SIGMOID,1> <<<gC, 256, SM1>>>(xrh, nullptr, wr2h, nullptr, r2, nullptr, Cv, Cv, nullptr, nullptr);
    hgemm_kernel<EPI_MULADD,1>  <<<gC, 256, SM1>>>(k2h, nullptr, wv2h, nullptr, out, nullptr, Cv, Iv, x1, r2);
}

// round 9
// speedup vs baseline: 4.9823x; 1.2529x over previous
#include <cuda_runtime.h>
#include <cuda_fp16.h>
#include <cstdint>

#define Bv 4
#define Tv 4096
#define Cv 1024
#define Iv 4096
#define Mv (Bv * Tv)          // 16384 tokens
#define NCHUNK 64
#define CLEN (Tv / NCHUNK)    // 64

typedef unsigned long long u64;
typedef unsigned int u32;

// ===========================================================================
// PTX helpers (sm_80-era only — bare compute_103 target rejects tcgen05)
// ===========================================================================
__device__ __forceinline__ u32 smem_to_u32(const void* p) {
    u32 a;
    asm("{ .reg .u64 t; cvta.to.shared.u64 t, %1; cvt.u32.u64 %0, t; }" : "=r"(a) : "l"(p));
    return a;
}
__device__ __forceinline__ void ldsm4(u32* r, u32 addr) {
    asm volatile("ldmatrix.sync.aligned.m8n8.x4.shared.b16 {%0,%1,%2,%3}, [%4];"
                 : "=r"(r[0]), "=r"(r[1]), "=r"(r[2]), "=r"(r[3]) : "r"(addr));
}
__device__ __forceinline__ void mma16816(float* c, const u32* a, const u32* b) {
    asm volatile("mma.sync.aligned.m16n8k16.row.col.f32.f16.f16.f32 "
                 "{%0,%1,%2,%3}, {%4,%5,%6,%7}, {%8,%9}, {%0,%1,%2,%3};"
                 : "+f"(c[0]), "+f"(c[1]), "+f"(c[2]), "+f"(c[3])
                 : "r"(a[0]), "r"(a[1]), "r"(a[2]), "r"(a[3]), "r"(b[0]), "r"(b[1]));
}
__device__ __forceinline__ void cpasync16(u32 s, const void* g) {
    asm volatile("cp.async.cg.shared.global [%0], [%1], 16;" :: "r"(s), "l"(g));
}
__device__ __forceinline__ void cpasync_commit() { asm volatile("cp.async.commit_group;" ::: "memory"); }
template<int N> __device__ __forceinline__ void cpasync_wait() {
    asm volatile("cp.async.wait_group %0;" :: "n"(N) : "memory");
}

// ===========================================================================
// Scratch (__device__ globals; allocation-free)
// ===========================================================================
__device__ float g_k  [(size_t)Mv * Cv];
__device__ float g_v  [(size_t)Mv * Cv];
__device__ float g_r  [(size_t)Mv * Cv];
__device__ float g_x1 [(size_t)Mv * Cv];
__device__ float g_r2 [(size_t)Mv * Cv];
__device__ float g_sA [Bv * NCHUNK * Cv];
__device__ float g_sB [Bv * NCHUNK * Cv];

__device__ __half a_xk_h[(size_t)Mv * Cv], a_xk_l[(size_t)Mv * Cv];   // k GEMM: 2-prod A-split; k2 GEMM uses hi only
__device__ __half a_xv_h[(size_t)Mv * Cv];                            // 1-prod
__device__ __half a_xr_h[(size_t)Mv * Cv];                            // 1-prod
__device__ __half a_rw_h[(size_t)Mv * Cv];                            // 1-prod
__device__ __half a_k2_h[(size_t)Mv * Iv];                            // 1-prod (v2 A side)

// weights transposed to [N,K] K-major fp16 (hi only — no B-side lo anywhere now)
__device__ __half w_k_h [Cv * Cv];
__device__ __half w_v_h [Cv * Cv];
__device__ __half w_r_h [Cv * Cv];
__device__ __half w_o_h [Cv * Cv];
__device__ __half w_r2_h[Cv * Cv];
__device__ __half w_k2_h[(size_t)Iv * Cv];
__device__ __half w_v2_h[(size_t)Cv * Iv];

// ===========================================================================
// Numeric helpers
// ===========================================================================
__device__ __forceinline__ float clip20(float x) { return fminf(fmaxf(x, -20.f), 20.f); }
__device__ __forceinline__ float sigm(float x)   { return 1.0f / (1.0f + __expf(-x)); }

__device__ __forceinline__ void split1(float v, uint16_t& h, uint16_t& l) {
    __half hb = __float2half_rn(v);
    float rr = v - __half2float(hb);
    __half lb = __float2half_rn(rr);
    h = *(uint16_t*)&hb; l = *(uint16_t*)&lb;
}
__device__ __forceinline__ u32 pack2h(float a, float b) {
    __half ha = __float2half_rn(a), hb = __float2half_rn(b);
    return (u32)(*(uint16_t*)&ha) | ((u32)(*(uint16_t*)&hb) << 16);
}
__device__ __forceinline__ void split4st(float4 v, __half* Hi, __half* Lo, size_t e) {
    uint16_t h0,l0,h1,l1,h2,l2,h3,l3;
    split1(v.x,h0,l0); split1(v.y,h1,l1); split1(v.z,h2,l2); split1(v.w,h3,l3);
    *reinterpret_cast<uint2*>(Hi + e) =
        make_uint2((u32)h0 | ((u32)h1 << 16), (u32)h2 | ((u32)h3 << 16));
    *reinterpret_cast<uint2*>(Lo + e) =
        make_uint2((u32)l0 | ((u32)l1 << 16), (u32)l2 | ((u32)l3 << 16));
}
__device__ __forceinline__ void round4st(float4 v, __half* Hi, size_t e) {
    *reinterpret_cast<uint2*>(Hi + e) = make_uint2(pack2h(v.x, v.y), pack2h(v.z, v.w));
}
__device__ __forceinline__ float4 mixf4(float4 m, float4 h, float4 s) {
    float4 o;
    o.x = m.x * h.x + (1.f - m.x) * s.x;
    o.y = m.y * h.y + (1.f - m.y) * s.y;
    o.z = m.z * h.z + (1.f - m.z) * s.z;
    o.w = m.w * h.w + (1.f - m.w) * s.w;
    return o;
}

// ===========================================================================
// Fused RMSNorm + token-shift mix (norms of rows t and t-1 computed in-kernel)
// ===========================================================================
__device__ __forceinline__ void norm2_reduce(float sc, float sp, float& oc, float& op) {
#pragma unroll
    for (int o = 16; o > 0; o >>= 1) {
        sc += __shfl_xor_sync(0xffffffffu, sc, o);
        sp += __shfl_xor_sync(0xffffffffu, sp, o);
    }
    __shared__ float rc[8], rp[8];
    const int tid = threadIdx.x;
    if ((tid & 31) == 0) { rc[tid >> 5] = sc; rp[tid >> 5] = sp; }
    __syncthreads();
    float tc = 0.f, tp = 0.f;
#pragma unroll
    for (int i = 0; i < 8; i++) { tc += rc[i]; tp += rp[i]; }
    oc = rsqrtf(tc * (1.0f / (float)Cv) + 1e-6f);
    op = rsqrtf(tp * (1.0f / (float)Cv) + 1e-6f);
}

__global__ void __launch_bounds__(256) fusedmix3_kernel(const float* __restrict__ x,
    const float* __restrict__ w,
    const float* __restrict__ mk, const float* __restrict__ mv, const float* __restrict__ mr,
    __half* kh, __half* kl, __half* vh, __half* rh)
{
    const int row = blockIdx.x, tid = threadIdx.x;
    const int t = row & (Tv - 1);
    const size_t i4 = (size_t)row * (Cv / 4) + tid;
    float4 xc = reinterpret_cast<const float4*>(x)[i4];
    float4 xp = make_float4(0.f, 0.f, 0.f, 0.f);
    if (t != 0) xp = reinterpret_cast<const float4*>(x)[i4 - (Cv / 4)];
    float sc, sp;
    norm2_reduce(xc.x*xc.x + xc.y*xc.y + xc.z*xc.z + xc.w*xc.w,
                 xp.x*xp.x + xp.y*xp.y + xp.z*xp.z + xp.w*xp.w, sc, sp);
    float4 wv = reinterpret_cast<const float4*>(w)[tid];
    float4 hv = make_float4(xc.x*sc*wv.x, xc.y*sc*wv.y, xc.z*sc*wv.z, xc.w*sc*wv.w);
    float4 sh = make_float4(xp.x*sp*wv.x, xp.y*sp*wv.y, xp.z*sp*wv.z, xp.w*sp*wv.w);
    const size_t e = i4 * 4;
    split4st(mixf4(reinterpret_cast<const float4*>(mk)[tid], hv, sh), kh, kl, e);
    round4st(mixf4(reinterpret_cast<const float4*>(mv)[tid], hv, sh), vh, e);
    round4st(mixf4(reinterpret_cast<const float4*>(mr)[tid], hv, sh), rh, e);
}

__global__ void __launch_bounds__(256) fusedmix2_kernel(const float* __restrict__ x,
    const float* __restrict__ w,
    const float* __restrict__ mk, const float* __restrict__ mr,
    __half* kh, __half* rh)
{
    const int row = blockIdx.x, tid = threadIdx.x;
    const int t = row & (Tv - 1);
    const size_t i4 = (size_t)row * (Cv / 4) + tid;
    float4 xc = reinterpret_cast<const float4*>(x)[i4];
    float4 xp = make_float4(0.f, 0.f, 0.f, 0.f);
    if (t != 0) xp = reinterpret_cast<const float4*>(x)[i4 - (Cv / 4)];
    float sc, sp;
    norm2_reduce(xc.x*xc.x + xc.y*xc.y + xc.z*xc.z + xc.w*xc.w,
                 xp.x*xp.x + xp.y*xp.y + xp.z*xp.z + xp.w*xp.w, sc, sp);
    float4 wv = reinterpret_cast<const float4*>(w)[tid];
    float4 hv = make_float4(xc.x*sc*wv.x, xc.y*sc*wv.y, xc.z*sc*wv.z, xc.w*sc*wv.w);
    float4 sh = make_float4(xp.x*sp*wv.x, xp.y*sp*wv.y, xp.z*sp*wv.z, xp.w*sp*wv.w);
    const size_t e = i4 * 4;
    round4st(mixf4(reinterpret_cast<const float4*>(mk)[tid], hv, sh), kh, e);
    round4st(mixf4(reinterpret_cast<const float4*>(mr)[tid], hv, sh), rh, e);
}

// ===========================================================================
// Weight transpose: W[K,N] fp32 -> [N,K] fp16 (rounded)
// ===========================================================================
__global__ void __launch_bounds__(256) wsplit_kernel(const float* __restrict__ W,
    __half* __restrict__ Whi, int K, int N)
{
    __shared__ float t[32][33];
    const int tx = threadIdx.x, ty = threadIdx.y;
    const int n0 = blockIdx.x * 32, k0 = blockIdx.y * 32;
#pragma unroll
    for (int i = ty; i < 32; i += 8)
        t[i][tx] = W[(size_t)(k0 + i) * N + n0 + tx];
    __syncthreads();
#pragma unroll
    for (int i = ty; i < 32; i += 8) {
        const float v = t[tx][i];                       // = W[k0+tx][n0+i]
        Whi[(size_t)(n0 + i) * K + k0 + tx] = __float2half_rn(v);
    }
}

// ===========================================================================
// WKV scan (3-pass chunked linear recurrence); pass3 emits r*wkv fp16
// ===========================================================================
__global__ void __launch_bounds__(1024) wkv_pass1(const float* __restrict__ k,
    const float* __restrict__ v, const float* __restrict__ td,
    float* __restrict__ sA, float* __restrict__ sB)
{
    const int c = threadIdx.x, chunk = blockIdx.x, b = blockIdx.y;
    const float ew = __expf(clip20(-__expf(td[c])));
    float a = 0.f, bb = 0.f;
    size_t base = ((size_t)(b * Tv) + (size_t)chunk * CLEN) * Cv + c;
    for (int t = 0; t < CLEN; t++) {
        const size_t ix = base + (size_t)t * Cv;
        const float kt = k[ix], vt = v[ix];
        const float ek = __expf(clip20(kt));
        a = ew * a + ek * vt;  bb = ew * bb + ek;
    }
    const int sidx = (b * NCHUNK + chunk) * Cv + c;
    sA[sidx] = a; sB[sidx] = bb;
}

__global__ void __launch_bounds__(1024) wkv_pass2(const float* __restrict__ td,
                                                  float* __restrict__ sA, float* __restrict__ sB)
{
    const int c = threadIdx.x, b = blockIdx.x;
    const float w = clip20(-__expf(td[c]));
    const float ewL = __expf(w * (float)CLEN);
    float Sa = 0.f, Sb = 0.f;
    for (int i = 0; i < NCHUNK; i++) {
        const int idx = (b * NCHUNK + i) * Cv + c;
        const float la = sA[idx], lb = sB[idx];
        sA[idx] = Sa; sB[idx] = Sb;
        Sa = ewL * Sa + la;  Sb = ewL * Sb + lb;
    }
}

__global__ void __launch_bounds__(1024) wkv_pass3(const float* __restrict__ k,
    const float* __restrict__ v, const float* __restrict__ r,
    const float* __restrict__ td, const float* __restrict__ tf,
    const float* __restrict__ sA, const float* __restrict__ sB,
    __half* __restrict__ oh)
{
    const int c = threadIdx.x, chunk = blockIdx.x, b = blockIdx.y;
    const float ew = __expf(clip20(-__expf(td[c])));
    const float u  = tf[c];
    const int sidx = (b * NCHUNK + chunk) * Cv + c;
    float a = sA[sidx], bb = sB[sidx];
    size_t base = ((size_t)(b * Tv) + (size_t)chunk * CLEN) * Cv + c;
    for (int t = 0; t < CLEN; t++) {
        const size_t ix = base + (size_t)t * Cv;
        const float kt = k[ix], vt = v[ix];
        const float ekt = __expf(clip20(u + kt));
        const float o = r[ix] * __fdividef(a + ekt * vt, bb + ekt + 1e-8f);
        oh[ix] = __float2half_rn(o);
        const float ek = __expf(clip20(kt));
        a = ew * a + ek * vt;  bb = ew * bb + ek;
    }
}

// ===========================================================================
// HMMA split-fp16 GEMM.
//   NPROD=1: D = Ah@Bh^T
//   NPROD=2: D = (Ah+Al)@Bh^T
// 128x128 tile, Kchunk=64, 3-stage cp.async, fragment double buffer.
// 8 warps: 4(m) x 2(n), warp tile 32x64.
// ===========================================================================
enum { EPI_NONE = 0, EPI_SIGMOID = 1, EPI_ADD = 2, EPI_MULADD = 3, EPI_RELUSQ_H = 4 };

__device__ __forceinline__ u32 swz(u32 o) { return o ^ ((o >> 3) & 0x70); }

struct Frags { u32 ah[2][4], al[2][4], bh[4][4]; };

template<int EPI, int NPROD>
__global__ void __launch_bounds__(256) hgemm_kernel(
    const __half* __restrict__ Ahi, const __half* __restrict__ Alo,
    const __half* __restrict__ Bhi,
    float* __restrict__ C, __half* __restrict__ Chi,
    int N, int K, const float* __restrict__ E1, const float* __restrict__ E2)
{
    constexpr int STAGE  = 16384 * (NPROD + 1);
    constexpr int OFF_AH = 0;
    constexpr int OFF_AL = 16384;                            // valid when NPROD==2
    constexpr int OFF_BH = (NPROD >= 2) ? 32768 : 16384;
    extern __shared__ __align__(1024) char smem[];
    const u32 sbase = smem_to_u32(smem);
    const int tid = threadIdx.x, wid = tid >> 5, lane = tid & 31;

    // ---- cp.async mapping: 2 threads/row, 4x16B each, per 16KB part
    const int lrow = tid >> 1;
    const int segb = (tid & 1) * 64;
    u32 soff[4];
#pragma unroll
    for (int j = 0; j < 4; j++) soff[j] = swz((u32)(lrow * 128 + segb + j * 16));
    const size_t pitch = (size_t)K * 2;
    const char* gAh = (const char*)Ahi + (size_t)(blockIdx.y * 128 + lrow) * pitch + segb;
    const char* gAl = (NPROD >= 2) ? (const char*)Alo + (size_t)(blockIdx.y * 128 + lrow) * pitch + segb : nullptr;
    const char* gBh = (const char*)Bhi + (size_t)(blockIdx.x * 128 + lrow) * pitch + segb;

    auto ld_chunk = [&](int stage, int c) {
        const u32 sb = sbase + stage * STAGE;
        const size_t go = (size_t)c * 128;   // 64 fp16 = 128 bytes per chunk
#pragma unroll
        for (int j = 0; j < 4; j++) cpasync16(sb + OFF_AH + soff[j], gAh + go + j * 16);
        if (NPROD >= 2) {
#pragma unroll
            for (int j = 0; j < 4; j++) cpasync16(sb + OFF_AL + soff[j], gAl + go + j * 16);
        }
#pragma unroll
        for (int j = 0; j < 4; j++) cpasync16(sb + OFF_BH + soff[j], gBh + go + j * 16);
        cpasync_commit();
    };

    // ---- warp tiling / ldmatrix lane addressing
    const int wm = (wid & 3) * 32;
    const int wn = (wid >> 2) * 64;
    const int laneA_row = lane & 15;
    const int laneA_kb  = (lane >> 4) * 16;
    const int laneB_row = (lane & 7) | (((lane >> 4) & 1) << 3);
    const int laneB_kb  = ((lane >> 3) & 1) * 16;

    auto ld_frags = [&](u32 sb, int ks, Frags& f) {
        const int kb = ks * 32;
#pragma unroll
        for (int i = 0; i < 2; i++) {
            const u32 o = swz((u32)((wm + 16 * i + laneA_row) * 128 + kb + laneA_kb));
            ldsm4(f.ah[i], sb + OFF_AH + o);
            if (NPROD >= 2) ldsm4(f.al[i], sb + OFF_AL + o);
        }
#pragma unroll
        for (int g = 0; g < 4; g++) {
            const u32 o = swz((u32)((wn + 16 * g + laneB_row) * 128 + kb + laneB_kb));
            ldsm4(f.bh[g], sb + OFF_BH + o);
        }
    };

    float acc[2][8][4];
#pragma unroll
    for (int i = 0; i < 2; i++)
#pragma unroll
        for (int j = 0; j < 8; j++)
#pragma unroll
            for (int q = 0; q < 4; q++) acc[i][j][q] = 0.f;

    auto mma_step = [&](Frags& f) {
#pragma unroll
        for (int i = 0; i < 2; i++)
#pragma unroll
            for (int j = 0; j < 8; j++) {
                const u32* Bh = &f.bh[j >> 1][(j & 1) * 2];
                mma16816(acc[i][j], f.ah[i], Bh);
                if (NPROD >= 2) mma16816(acc[i][j], f.al[i], Bh);
            }
    };

    const int nch = K >> 6;
    ld_chunk(0, 0); ld_chunk(1, 1); ld_chunk(2, 2);

    Frags fr[2];
    for (int c = 0; c < nch; ++c) {
        if      (c + 2 < nch) cpasync_wait<2>();
        else if (c + 1 < nch) cpasync_wait<1>();
        else                  cpasync_wait<0>();
        __syncthreads();

        const u32 sb = sbase + (c % 3) * STAGE;
        ld_frags(sb, 0, fr[0]);
#pragma unroll
        for (int ks = 0; ks < 4; ++ks) {
            if (ks < 3) ld_frags(sb, ks + 1, fr[(ks + 1) & 1]);
            mma_step(fr[ks & 1]);
        }
        __syncthreads();
        if (c + 3 < nch) ld_chunk(c % 3, c + 3);
    }

    // ---- epilogue: frag (i,j) -> rows bm+wm+16i+{gid,gid+8}, cols bn+wn+8j+2tg
    const int gid = lane >> 2, tg = lane & 3;
    const int bm = blockIdx.y * 128, bn = blockIdx.x * 128;
#pragma unroll
    for (int i = 0; i < 2; i++) {
        const int r0 = bm + wm + 16 * i + gid;
#pragma unroll
        for (int j = 0; j < 8; j++) {
            const int cc = bn + wn + 8 * j + 2 * tg;
            const size_t idx0 = (size_t)r0 * N + cc;
            const size_t idx1 = idx0 + (size_t)8 * N;
            float v0 = acc[i][j][0], v1 = acc[i][j][1];
            float v2 = acc[i][j][2], v3 = acc[i][j][3];
            if (EPI == EPI_RELUSQ_H) {
                v0 = fmaxf(v0, 0.f); v0 *= v0;  v1 = fmaxf(v1, 0.f); v1 *= v1;
                v2 = fmaxf(v2, 0.f); v2 *= v2;  v3 = fmaxf(v3, 0.f); v3 *= v3;
                *reinterpret_cast<u32*>(Chi + idx0) = pack2h(v0, v1);
                *reinterpret_cast<u32*>(Chi + idx1) = pack2h(v2, v3);
            } else {
                if (EPI == EPI_SIGMOID) {
                    v0 = sigm(v0); v1 = sigm(v1); v2 = sigm(v2); v3 = sigm(v3);
                } else if (EPI == EPI_ADD) {
                    const float2 e0 = *reinterpret_cast<const float2*>(&E1[idx0]);
                    const float2 e1 = *reinterpret_cast<const float2*>(&E1[idx1]);
                    v0 += e0.x; v1 += e0.y; v2 += e1.x; v3 += e1.y;
                } else if (EPI == EPI_MULADD) {
                    const float2 a0 = *reinterpret_cast<const float2*>(&E1[idx0]);
                    const float2 a1 = *reinterpret_cast<const float2*>(&E1[idx1]);
                    const float2 m0 = *reinterpret_cast<const float2*>(&E2[idx0]);
                    const float2 m1 = *reinterpret_cast<const float2*>(&E2[idx1]);
                    v0 = a0.x + m0.x * v0; v1 = a0.y + m0.y * v1;
                    v2 = a1.x + m1.x * v2; v3 = a1.y + m1.y * v3;
                }
                *reinterpret_cast<float2*>(&C[idx0]) = make_float2(v0, v1);
                *reinterpret_cast<float2*>(&C[idx1]) = make_float2(v2, v3);
            }
        }
    }
}

// ===========================================================================
// Launch
// ===========================================================================
extern "C" void kernel_launch(void* const* d_in, const int* in_sizes, int n_in,
                              void* d_out, int out_size)
{
    const float* x     = (const float*)d_in[0];
    const float* ln1_w = (const float*)d_in[1];
    const float* ln2_w = (const float*)d_in[2];
    const float* td    = (const float*)d_in[3];
    const float* tf    = (const float*)d_in[4];
    const float* mk    = (const float*)d_in[5];
    const float* mv    = (const float*)d_in[6];
    const float* mr    = (const float*)d_in[7];
    const float* Wk    = (const float*)d_in[8];
    const float* Wv    = (const float*)d_in[9];
    const float* Wr    = (const float*)d_in[10];
    const float* Wo    = (const float*)d_in[11];
    const float* mk2   = (const float*)d_in[12];
    const float* mr2   = (const float*)d_in[13];
    const float* Wk2   = (const float*)d_in[14];
    const float* Wv2   = (const float*)d_in[15];
    const float* Wr2   = (const float*)d_in[16];
    float* out = (float*)d_out;

#define SYM(p, s) void* p##_; cudaGetSymbolAddress(&p##_, s); auto* p = (decltype(&s[0]))p##_
    SYM(k,   g_k);  SYM(v,   g_v);  SYM(r,   g_r);
    SYM(x1,  g_x1); SYM(r2,  g_r2); SYM(sA,  g_sA); SYM(sB,  g_sB);
    SYM(xkh, a_xk_h); SYM(xkl, a_xk_l); SYM(xvh, a_xv_h); SYM(xrh, a_xr_h);
    SYM(rwh, a_rw_h); SYM(k2h, a_k2_h);
    SYM(wkh, w_k_h);  SYM(wvh, w_v_h);  SYM(wrh, w_r_h);  SYM(woh, w_o_h);
    SYM(wr2h, w_r2_h); SYM(wk2h, w_k2_h); SYM(wv2h, w_v2_h);
#undef SYM

    const int SM2 = 3 * 49152, SM1 = 3 * 32768;
    cudaFuncSetAttribute(hgemm_kernel<EPI_NONE,2>,     cudaFuncAttributeMaxDynamicSharedMemorySize, SM2);
    cudaFuncSetAttribute(hgemm_kernel<EPI_NONE,1>,     cudaFuncAttributeMaxDynamicSharedMemorySize, SM1);
    cudaFuncSetAttribute(hgemm_kernel<EPI_SIGMOID,1>,  cudaFuncAttributeMaxDynamicSharedMemorySize, SM1);
    cudaFuncSetAttribute(hgemm_kernel<EPI_ADD,1>,      cudaFuncAttributeMaxDynamicSharedMemorySize, SM1);
    cudaFuncSetAttribute(hgemm_kernel<EPI_MULADD,1>,   cudaFuncAttributeMaxDynamicSharedMemorySize, SM1);
    cudaFuncSetAttribute(hgemm_kernel<EPI_RELUSQ_H,1>, cudaFuncAttributeMaxDynamicSharedMemorySize, SM1);

    const dim3 tb(32, 8);
    wsplit_kernel<<<dim3(Cv/32, Cv/32), tb>>>(Wk,  wkh,  Cv, Cv);
    wsplit_kernel<<<dim3(Cv/32, Cv/32), tb>>>(Wv,  wvh,  Cv, Cv);
    wsplit_kernel<<<dim3(Cv/32, Cv/32), tb>>>(Wr,  wrh,  Cv, Cv);
    wsplit_kernel<<<dim3(Cv/32, Cv/32), tb>>>(Wo,  woh,  Cv, Cv);
    wsplit_kernel<<<dim3(Cv/32, Cv/32), tb>>>(Wr2, wr2h, Cv, Cv);
    wsplit_kernel<<<dim3(Iv/32, Cv/32), tb>>>(Wk2, wk2h, Cv, Iv);  // [I,C]
    wsplit_kernel<<<dim3(Cv/32, Iv/32), tb>>>(Wv2, wv2h, Iv, Cv);  // [C,I]

    const dim3 gC(Cv / 128, Mv / 128);   // (8, 128)
    const dim3 gI(Iv / 128, Mv / 128);   // (32, 128)

    // --- time mixing ---
    fusedmix3_kernel<<<Mv, 256>>>(x, ln1_w, mk, mv, mr, xkh, xkl, xvh, xrh);
    hgemm_kernel<EPI_NONE,2>   <<<gC, 256, SM2>>>(xkh, xkl, wkh, k, nullptr, Cv, Cv, nullptr, nullptr);
    hgemm_kernel<EPI_NONE,1>   <<<gC, 256, SM1>>>(xvh, nullptr, wvh, v, nullptr, Cv, Cv, nullptr, nullptr);
    hgemm_kernel<EPI_SIGMOID,1><<<gC, 256, SM1>>>(xrh, nullptr, wrh, r, nullptr, Cv, Cv, nullptr, nullptr);
    wkv_pass1<<<dim3(NCHUNK, Bv), Cv>>>(k, v, td, sA, sB);
    wkv_pass2<<<Bv, Cv>>>(td, sA, sB);
    wkv_pass3<<<dim3(NCHUNK, Bv), Cv>>>(k, v, r, td, tf, sA, sB, rwh);
    hgemm_kernel<EPI_ADD,1>    <<<gC, 256, SM1>>>(rwh, nullptr, woh, x1, nullptr, Cv, Cv, x, nullptr);

    // --- channel mixing ---
    fusedmix2_kernel<<<Mv, 256>>>(x1, ln2_w, mk2, mr2, xkh, xrh);
    hgemm_kernel<EPI_RELUSQ_H,1><<<gI, 256, SM1>>>(xkh, nullptr, wk2h, nullptr, k2h, Iv, Cv, nullptr, nullptr);
    hgemm_kernel<EPI_SIGMOID,1> <<<gC, 256, SM1>>>(xrh, nullptr, wr2h, r2, nullptr, Cv, Cv, nullptr, nullptr);
    hgemm_kernel<EPI_MULADD,1>  <<<gC, 256, SM1>>>(k2h, nullptr, wv2h, out, nullptr, Cv, Iv, x1, r2);
}

// round 10
// speedup vs baseline: 5.6467x; 1.1334x over previous
#include <cuda_runtime.h>
#include <cuda_fp16.h>
#include <cstdint>

#define Bv 4
#define Tv 4096
#define Cv 1024
#define Iv 4096
#define Mv (Bv * Tv)          // 16384 tokens
#define NCHUNK 64
#define CLEN (Tv / NCHUNK)    // 64

typedef unsigned int u32;

// ===========================================================================
// PTX helpers (sm_80-era only — bare compute_103 target rejects tcgen05)
// ===========================================================================
__device__ __forceinline__ u32 smem_to_u32(const void* p) {
    u32 a;
    asm("{ .reg .u64 t; cvta.to.shared.u64 t, %1; cvt.u32.u64 %0, t; }" : "=r"(a) : "l"(p));
    return a;
}
__device__ __forceinline__ void ldsm4(u32* r, u32 addr) {
    asm volatile("ldmatrix.sync.aligned.m8n8.x4.shared.b16 {%0,%1,%2,%3}, [%4];"
                 : "=r"(r[0]), "=r"(r[1]), "=r"(r[2]), "=r"(r[3]) : "r"(addr));
}
__device__ __forceinline__ void mma16816(float* c, const u32* a, const u32* b) {
    asm volatile("mma.sync.aligned.m16n8k16.row.col.f32.f16.f16.f32 "
                 "{%0,%1,%2,%3}, {%4,%5,%6,%7}, {%8,%9}, {%0,%1,%2,%3};"
                 : "+f"(c[0]), "+f"(c[1]), "+f"(c[2]), "+f"(c[3])
                 : "r"(a[0]), "r"(a[1]), "r"(a[2]), "r"(a[3]), "r"(b[0]), "r"(b[1]));
}
__device__ __forceinline__ void cpasync16(u32 s, const void* g) {
    asm volatile("cp.async.cg.shared.global [%0], [%1], 16;" :: "r"(s), "l"(g));
}
__device__ __forceinline__ void cpasync_commit() { asm volatile("cp.async.commit_group;" ::: "memory"); }
template<int N> __device__ __forceinline__ void cpasync_wait() {
    asm volatile("cp.async.wait_group %0;" :: "n"(N) : "memory");
}

// ===========================================================================
// Scratch (__device__ globals; allocation-free)
// ===========================================================================
__device__ float g_ek [(size_t)Mv * Cv];      // exp(clip(k)) — written by k-GEMM epilogue
__device__ float g_v  [(size_t)Mv * Cv];
__device__ float g_r  [(size_t)Mv * Cv];
__device__ float g_x1 [(size_t)Mv * Cv];
__device__ float g_r2 [(size_t)Mv * Cv];
__device__ float g_sA [Bv * NCHUNK * Cv];
__device__ float g_sB [Bv * NCHUNK * Cv];

__device__ __half a_xk_h[(size_t)Mv * Cv];
__device__ __half a_xv_h[(size_t)Mv * Cv];
__device__ __half a_xr_h[(size_t)Mv * Cv];
__device__ __half a_rw_h[(size_t)Mv * Cv];
__device__ __half a_k2_h[(size_t)Mv * Iv];

// weights transposed to [N,K] K-major fp16
__device__ __half w_k_h [Cv * Cv];
__device__ __half w_v_h [Cv * Cv];
__device__ __half w_r_h [Cv * Cv];
__device__ __half w_o_h [Cv * Cv];
__device__ __half w_r2_h[Cv * Cv];
__device__ __half w_k2_h[(size_t)Iv * Cv];
__device__ __half w_v2_h[(size_t)Cv * Iv];

// ===========================================================================
// Numeric helpers
// ===========================================================================
#define EXP20F 4.851652e8f
__device__ __forceinline__ float clip20(float x) { return fminf(fmaxf(x, -20.f), 20.f); }
__device__ __forceinline__ float sigm(float x)   { return 1.0f / (1.0f + __expf(-x)); }

__device__ __forceinline__ u32 pack2h(float a, float b) {
    __half ha = __float2half_rn(a), hb = __float2half_rn(b);
    return (u32)(*(uint16_t*)&ha) | ((u32)(*(uint16_t*)&hb) << 16);
}
__device__ __forceinline__ void round4st(float4 v, __half* Hi, size_t e) {
    *reinterpret_cast<uint2*>(Hi + e) = make_uint2(pack2h(v.x, v.y), pack2h(v.z, v.w));
}
__device__ __forceinline__ float4 mixf4(float4 m, float4 h, float4 s) {
    float4 o;
    o.x = m.x * h.x + (1.f - m.x) * s.x;
    o.y = m.y * h.y + (1.f - m.y) * s.y;
    o.z = m.z * h.z + (1.f - m.z) * s.z;
    o.w = m.w * h.w + (1.f - m.w) * s.w;
    return o;
}

// ===========================================================================
// Fused RMSNorm + token-shift mix (all outputs rounded fp16 — all GEMMs 1-prod)
// ===========================================================================
__device__ __forceinline__ void norm2_reduce(float sc, float sp, float& oc, float& op) {
#pragma unroll
    for (int o = 16; o > 0; o >>= 1) {
        sc += __shfl_xor_sync(0xffffffffu, sc, o);
        sp += __shfl_xor_sync(0xffffffffu, sp, o);
    }
    __shared__ float rc[8], rp[8];
    const int tid = threadIdx.x;
    if ((tid & 31) == 0) { rc[tid >> 5] = sc; rp[tid >> 5] = sp; }
    __syncthreads();
    float tc = 0.f, tp = 0.f;
#pragma unroll
    for (int i = 0; i < 8; i++) { tc += rc[i]; tp += rp[i]; }
    oc = rsqrtf(tc * (1.0f / (float)Cv) + 1e-6f);
    op = rsqrtf(tp * (1.0f / (float)Cv) + 1e-6f);
}

__global__ void __launch_bounds__(256) fusedmix3_kernel(const float* __restrict__ x,
    const float* __restrict__ w,
    const float* __restrict__ mk, const float* __restrict__ mv, const float* __restrict__ mr,
    __half* kh, __half* vh, __half* rh)
{
    const int row = blockIdx.x, tid = threadIdx.x;
    const int t = row & (Tv - 1);
    const size_t i4 = (size_t)row * (Cv / 4) + tid;
    float4 xc = reinterpret_cast<const float4*>(x)[i4];
    float4 xp = make_float4(0.f, 0.f, 0.f, 0.f);
    if (t != 0) xp = reinterpret_cast<const float4*>(x)[i4 - (Cv / 4)];
    float sc, sp;
    norm2_reduce(xc.x*xc.x + xc.y*xc.y + xc.z*xc.z + xc.w*xc.w,
                 xp.x*xp.x + xp.y*xp.y + xp.z*xp.z + xp.w*xp.w, sc, sp);
    float4 wv = reinterpret_cast<const float4*>(w)[tid];
    float4 hv = make_float4(xc.x*sc*wv.x, xc.y*sc*wv.y, xc.z*sc*wv.z, xc.w*sc*wv.w);
    float4 sh = make_float4(xp.x*sp*wv.x, xp.y*sp*wv.y, xp.z*sp*wv.z, xp.w*sp*wv.w);
    const size_t e = i4 * 4;
    round4st(mixf4(reinterpret_cast<const float4*>(mk)[tid], hv, sh), kh, e);
    round4st(mixf4(reinterpret_cast<const float4*>(mv)[tid], hv, sh), vh, e);
    round4st(mixf4(reinterpret_cast<const float4*>(mr)[tid], hv, sh), rh, e);
}

__global__ void __launch_bounds__(256) fusedmix2_kernel(const float* __restrict__ x,
    const float* __restrict__ w,
    const float* __restrict__ mk, const float* __restrict__ mr,
    __half* kh, __half* rh)
{
    const int row = blockIdx.x, tid = threadIdx.x;
    const int t = row & (Tv - 1);
    const size_t i4 = (size_t)row * (Cv / 4) + tid;
    float4 xc = reinterpret_cast<const float4*>(x)[i4];
    float4 xp = make_float4(0.f, 0.f, 0.f, 0.f);
    if (t != 0) xp = reinterpret_cast<const float4*>(x)[i4 - (Cv / 4)];
    float sc, sp;
    norm2_reduce(xc.x*xc.x + xc.y*xc.y + xc.z*xc.z + xc.w*xc.w,
                 xp.x*xp.x + xp.y*xp.y + xp.z*xp.z + xp.w*xp.w, sc, sp);
    float4 wv = reinterpret_cast<const float4*>(w)[tid];
    float4 hv = make_float4(xc.x*sc*wv.x, xc.y*sc*wv.y, xc.z*sc*wv.z, xc.w*sc*wv.w);
    float4 sh = make_float4(xp.x*sp*wv.x, xp.y*sp*wv.y, xp.z*sp*wv.z, xp.w*sp*wv.w);
    const size_t e = i4 * 4;
    round4st(mixf4(reinterpret_cast<const float4*>(mk)[tid], hv, sh), kh, e);
    round4st(mixf4(reinterpret_cast<const float4*>(mr)[tid], hv, sh), rh, e);
}

// ===========================================================================
// Weight transpose: W[K,N] fp32 -> [N,K] fp16
// ===========================================================================
__device__ __forceinline__ void wtrans_body(const float* W, __half* D, int K, int N) {
    __shared__ float t[32][33];
    const int tx = threadIdx.x, ty = threadIdx.y;
    const int n0 = blockIdx.x * 32, k0 = blockIdx.y * 32;
#pragma unroll
    for (int i = ty; i < 32; i += 8)
        t[i][tx] = W[(size_t)(k0 + i) * N + n0 + tx];
    __syncthreads();
#pragma unroll
    for (int i = ty; i < 32; i += 8)
        D[(size_t)(n0 + i) * K + k0 + tx] = __float2half_rn(t[tx][i]);
}

__global__ void __launch_bounds__(256) wsplit5_kernel(
    const float* s0, const float* s1, const float* s2, const float* s3, const float* s4,
    __half* d0, __half* d1, __half* d2, __half* d3, __half* d4)
{
    const float* S; __half* D;
    switch (blockIdx.z) {
        case 0: S = s0; D = d0; break;
        case 1: S = s1; D = d1; break;
        case 2: S = s2; D = d2; break;
        case 3: S = s3; D = d3; break;
        default: S = s4; D = d4; break;
    }
    wtrans_body(S, D, Cv, Cv);
}

__global__ void __launch_bounds__(256) wsplit_kernel(const float* __restrict__ W,
    __half* __restrict__ D, int K, int N)
{
    wtrans_body(W, D, K, N);
}

// ===========================================================================
// WKV scan — exp-free (reads ek = exp(clip(k)) precomputed by k-GEMM epilogue)
// ===========================================================================
__global__ void __launch_bounds__(1024) wkv_pass1(const float* __restrict__ ek,
    const float* __restrict__ v, const float* __restrict__ td,
    float* __restrict__ sA, float* __restrict__ sB)
{
    const int c = threadIdx.x, chunk = blockIdx.x, b = blockIdx.y;
    const float ew = __expf(clip20(-__expf(td[c])));
    float a = 0.f, bb = 0.f;
    size_t base = ((size_t)(b * Tv) + (size_t)chunk * CLEN) * Cv + c;
    for (int t = 0; t < CLEN; t++) {
        const size_t ix = base + (size_t)t * Cv;
        const float e = ek[ix];
        a = ew * a + e * v[ix];  bb = ew * bb + e;
    }
    const int sidx = (b * NCHUNK + chunk) * Cv + c;
    sA[sidx] = a; sB[sidx] = bb;
}

__global__ void __launch_bounds__(1024) wkv_pass2(const float* __restrict__ td,
                                                  float* __restrict__ sA, float* __restrict__ sB)
{
    const int c = threadIdx.x, b = blockIdx.x;
    const float w = clip20(-__expf(td[c]));
    const float ewL = __expf(w * (float)CLEN);
    float Sa = 0.f, Sb = 0.f;
    for (int i = 0; i < NCHUNK; i++) {
        const int idx = (b * NCHUNK + i) * Cv + c;
        const float la = sA[idx], lb = sB[idx];
        sA[idx] = Sa; sB[idx] = Sb;
        Sa = ewL * Sa + la;  Sb = ewL * Sb + lb;
    }
}

__global__ void __launch_bounds__(1024) wkv_pass3(const float* __restrict__ ek,
    const float* __restrict__ v, const float* __restrict__ r,
    const float* __restrict__ td, const float* __restrict__ tf,
    const float* __restrict__ sA, const float* __restrict__ sB,
    __half* __restrict__ oh)
{
    const int c = threadIdx.x, chunk = blockIdx.x, b = blockIdx.y;
    const float ew = __expf(clip20(-__expf(td[c])));
    const float eu = __expf(tf[c]);
    const int sidx = (b * NCHUNK + chunk) * Cv + c;
    float a = sA[sidx], bb = sB[sidx];
    size_t base = ((size_t)(b * Tv) + (size_t)chunk * CLEN) * Cv + c;
    for (int t = 0; t < CLEN; t++) {
        const size_t ix = base + (size_t)t * Cv;
        const float e = ek[ix], vt = v[ix];
        const float ekt = fminf(eu * e, EXP20F);   // = exp(clip(u+k)); clip never active for |k|<~6
        const float o = r[ix] * __fdividef(a + ekt * vt, bb + ekt + 1e-8f);
        oh[ix] = __float2half_rn(o);
        a = ew * a + e * vt;  bb = ew * bb + e;
    }
}

// ===========================================================================
// HMMA fp16 GEMM core: 128x128 tile, Kchunk=64, 3-stage cp.async, 2 CTAs/SM.
// 8 warps: 4(m) x 2(n), warp tile 32x64.  D = A[M,K] @ B^T (B stored [N,K]).
// ===========================================================================
#define STAGE_B 32768
#define GSMEM   (3 * STAGE_B)

__device__ __forceinline__ u32 swz(u32 o) { return o ^ ((o >> 3) & 0x70); }

template<int KDIM>
__device__ __forceinline__ void gemm_core(const __half* Abase, const __half* Bbase,
                                          int arow0, int brow0, char* smem,
                                          float acc[2][8][4])
{
    const u32 sbase = smem_to_u32(smem);
    const int tid = threadIdx.x, wid = tid >> 5, lane = tid & 31;

    const int lrow = tid >> 1;
    const int segb = (tid & 1) * 64;
    u32 soff[4];
#pragma unroll
    for (int j = 0; j < 4; j++) soff[j] = swz((u32)(lrow * 128 + segb + j * 16));
    const char* gA = (const char*)(Abase + (size_t)(arow0 + lrow) * KDIM) + segb;
    const char* gB = (const char*)(Bbase + (size_t)(brow0 + lrow) * KDIM) + segb;

    auto ld_chunk = [&](int stage, int c) {
        const u32 sb = sbase + stage * STAGE_B;
        const size_t go = (size_t)c * 128;
#pragma unroll
        for (int j = 0; j < 4; j++) cpasync16(sb + soff[j], gA + go + j * 16);
#pragma unroll
        for (int j = 0; j < 4; j++) cpasync16(sb + 16384 + soff[j], gB + go + j * 16);
        cpasync_commit();
    };

    const int wm = (wid & 3) * 32;
    const int wn = (wid >> 2) * 64;
    const int laneA_row = lane & 15;
    const int laneA_kb  = (lane >> 4) * 16;
    const int laneB_row = (lane & 7) | (((lane >> 4) & 1) << 3);
    const int laneB_kb  = ((lane >> 3) & 1) * 16;

#pragma unroll
    for (int i = 0; i < 2; i++)
#pragma unroll
        for (int j = 0; j < 8; j++)
#pragma unroll
            for (int q = 0; q < 4; q++) acc[i][j][q] = 0.f;

    constexpr int nch = KDIM >> 6;
    ld_chunk(0, 0); ld_chunk(1, 1); ld_chunk(2, 2);

    for (int c = 0; c < nch; ++c) {
        if      (c + 2 < nch) cpasync_wait<2>();
        else if (c + 1 < nch) cpasync_wait<1>();
        else                  cpasync_wait<0>();
        __syncthreads();

        const u32 sb = sbase + (c % 3) * STAGE_B;
#pragma unroll
        for (int ks = 0; ks < 4; ++ks) {
            const int kb = ks * 32;
            u32 ah[2][4], bh[4][4];
#pragma unroll
            for (int i = 0; i < 2; i++)
                ldsm4(ah[i], sb + swz((u32)((wm + 16 * i + laneA_row) * 128 + kb + laneA_kb)));
#pragma unroll
            for (int g = 0; g < 4; g++)
                ldsm4(bh[g], sb + 16384 + swz((u32)((wn + 16 * g + laneB_row) * 128 + kb + laneB_kb)));
#pragma unroll
            for (int i = 0; i < 2; i++)
#pragma unroll
                for (int j = 0; j < 8; j++)
                    mma16816(acc[i][j], ah[i], &bh[j >> 1][(j & 1) * 2]);
        }
        __syncthreads();
        if (c + 3 < nch) ld_chunk(c % 3, c + 3);
    }
}

// epilogue addressing: frag (i,j) -> rows r0=16i+gid (+8), cols wn+8j+2tg
#define EPI_SETUP() \
    const int wid = threadIdx.x >> 5, lane = threadIdx.x & 31; \
    const int wm = (wid & 3) * 32, wn = (wid >> 2) * 64; \
    const int gid = lane >> 2, tg = lane & 3;

// ---- fused k/v/r GEMM: grid (24, 128); x in [0,8)=k->exp, [8,16)=v, [16,24)=r->sigm
__global__ void __launch_bounds__(256, 2) hgemm_kvr(
    const __half* __restrict__ A0, const __half* __restrict__ A1, const __half* __restrict__ A2,
    const __half* __restrict__ B0, const __half* __restrict__ B1, const __half* __restrict__ B2,
    float* __restrict__ C0, float* __restrict__ C1, float* __restrict__ C2)
{
    extern __shared__ __align__(1024) char smem[];
    const int sel = blockIdx.x >> 3;
    const int bxe = blockIdx.x & 7;
    const __half* A = (sel == 0) ? A0 : ((sel == 1) ? A1 : A2);
    const __half* B = (sel == 0) ? B0 : ((sel == 1) ? B1 : B2);
    float*       C = (sel == 0) ? C0 : ((sel == 1) ? C1 : C2);

    float acc[2][8][4];
    gemm_core<Cv>(A, B, blockIdx.y * 128, bxe * 128, smem, acc);

    EPI_SETUP();
    const int bm = blockIdx.y * 128, bn = bxe * 128;
#pragma unroll
    for (int i = 0; i < 2; i++) {
        const int r0 = bm + wm + 16 * i + gid;
#pragma unroll
        for (int j = 0; j < 8; j++) {
            const int cc = bn + wn + 8 * j + 2 * tg;
            const size_t idx0 = (size_t)r0 * Cv + cc;
            const size_t idx1 = idx0 + (size_t)8 * Cv;
            float v0 = acc[i][j][0], v1 = acc[i][j][1];
            float v2 = acc[i][j][2], v3 = acc[i][j][3];
            if (sel == 0) {
                v0 = __expf(clip20(v0)); v1 = __expf(clip20(v1));
                v2 = __expf(clip20(v2)); v3 = __expf(clip20(v3));
            } else if (sel == 2) {
                v0 = sigm(v0); v1 = sigm(v1); v2 = sigm(v2); v3 = sigm(v3);
            }
            *reinterpret_cast<float2*>(&C[idx0]) = make_float2(v0, v1);
            *reinterpret_cast<float2*>(&C[idx1]) = make_float2(v2, v3);
        }
    }
}

// ---- Wo GEMM: x1 = x + rw@Wo^T
__global__ void __launch_bounds__(256, 2) hgemm_add(
    const __half* __restrict__ A, const __half* __restrict__ B,
    float* __restrict__ C, const float* __restrict__ E)
{
    extern __shared__ __align__(1024) char smem[];
    float acc[2][8][4];
    gemm_core<Cv>(A, B, blockIdx.y * 128, blockIdx.x * 128, smem, acc);

    EPI_SETUP();
    const int bm = blockIdx.y * 128, bn = blockIdx.x * 128;
#pragma unroll
    for (int i = 0; i < 2; i++) {
        const int r0 = bm + wm + 16 * i + gid;
#pragma unroll
        for (int j = 0; j < 8; j++) {
            const int cc = bn + wn + 8 * j + 2 * tg;
            const size_t idx0 = (size_t)r0 * Cv + cc;
            const size_t idx1 = idx0 + (size_t)8 * Cv;
            const float2 e0 = *reinterpret_cast<const float2*>(&E[idx0]);
            const float2 e1 = *reinterpret_cast<const float2*>(&E[idx1]);
            *reinterpret_cast<float2*>(&C[idx0]) = make_float2(acc[i][j][0] + e0.x, acc[i][j][1] + e0.y);
            *reinterpret_cast<float2*>(&C[idx1]) = make_float2(acc[i][j][2] + e1.x, acc[i][j][3] + e1.y);
        }
    }
}

// ---- fused k2/r2 GEMM: grid (40, 128); x<32: k2=relu^2 (fp16, N=Iv); x>=32: r2=sigm (fp32, N=Cv)
__global__ void __launch_bounds__(256, 2) hgemm_k2r2(
    const __half* __restrict__ A0, const __half* __restrict__ A1,
    const __half* __restrict__ B0, const __half* __restrict__ B1,
    __half* __restrict__ C0, float* __restrict__ C1)
{
    extern __shared__ __align__(1024) char smem[];
    const bool isr2 = (blockIdx.x >= 32);
    const int bxe = isr2 ? (blockIdx.x - 32) : blockIdx.x;
    const __half* A = isr2 ? A1 : A0;
    const __half* B = isr2 ? B1 : B0;

    float acc[2][8][4];
    gemm_core<Cv>(A, B, blockIdx.y * 128, bxe * 128, smem, acc);

    EPI_SETUP();
    const int bm = blockIdx.y * 128, bn = bxe * 128;
    const int N = isr2 ? Cv : Iv;
#pragma unroll
    for (int i = 0; i < 2; i++) {
        const int r0 = bm + wm + 16 * i + gid;
#pragma unroll
        for (int j = 0; j < 8; j++) {
            const int cc = bn + wn + 8 * j + 2 * tg;
            const size_t idx0 = (size_t)r0 * N + cc;
            const size_t idx1 = idx0 + (size_t)8 * N;
            float v0 = acc[i][j][0], v1 = acc[i][j][1];
            float v2 = acc[i][j][2], v3 = acc[i][j][3];
            if (!isr2) {
                v0 = fmaxf(v0, 0.f); v0 *= v0;  v1 = fmaxf(v1, 0.f); v1 *= v1;
                v2 = fmaxf(v2, 0.f); v2 *= v2;  v3 = fmaxf(v3, 0.f); v3 *= v3;
                *reinterpret_cast<u32*>(C0 + idx0) = pack2h(v0, v1);
                *reinterpret_cast<u32*>(C0 + idx1) = pack2h(v2, v3);
            } else {
                *reinterpret_cast<float2*>(&C1[idx0]) = make_float2(sigm(v0), sigm(v1));
                *reinterpret_cast<float2*>(&C1[idx1]) = make_float2(sigm(v2), sigm(v3));
            }
        }
    }
}

// ---- v2 GEMM (K=Iv): out = x1 + r2 * (k2@Wv2^T)
__global__ void __launch_bounds__(256, 2) hgemm_muladd(
    const __half* __restrict__ A, const __half* __restrict__ B,
    float* __restrict__ C, const float* __restrict__ E1, const float* __restrict__ E2)
{
    extern __shared__ __align__(1024) char smem[];
    float acc[2][8][4];
    gemm_core<Iv>(A, B, blockIdx.y * 128, blockIdx.x * 128, smem, acc);

    EPI_SETUP();
    const int bm = blockIdx.y * 128, bn = blockIdx.x * 128;
#pragma unroll
    for (int i = 0; i < 2; i++) {
        const int r0 = bm + wm + 16 * i + gid;
#pragma unroll
        for (int j = 0; j < 8; j++) {
            const int cc = bn + wn + 8 * j + 2 * tg;
            const size_t idx0 = (size_t)r0 * Cv + cc;
            const size_t idx1 = idx0 + (size_t)8 * Cv;
            const float2 a0 = *reinterpret_cast<const float2*>(&E1[idx0]);
            const float2 a1 = *reinterpret_cast<const float2*>(&E1[idx1]);
            const float2 m0 = *reinterpret_cast<const float2*>(&E2[idx0]);
            const float2 m1 = *reinterpret_cast<const float2*>(&E2[idx1]);
            *reinterpret_cast<float2*>(&C[idx0]) =
                make_float2(a0.x + m0.x * acc[i][j][0], a0.y + m0.y * acc[i][j][1]);
            *reinterpret_cast<float2*>(&C[idx1]) =
                make_float2(a1.x + m1.x * acc[i][j][2], a1.y + m1.y * acc[i][j][3]);
        }
    }
}

// ===========================================================================
// Launch
// ===========================================================================
extern "C" void kernel_launch(void* const* d_in, const int* in_sizes, int n_in,
                              void* d_out, int out_size)
{
    const float* x     = (const float*)d_in[0];
    const float* ln1_w = (const float*)d_in[1];
    const float* ln2_w = (const float*)d_in[2];
    const float* td    = (const float*)d_in[3];
    const float* tf    = (const float*)d_in[4];
    const float* mk    = (const float*)d_in[5];
    const float* mv    = (const float*)d_in[6];
    const float* mr    = (const float*)d_in[7];
    const float* Wk    = (const float*)d_in[8];
    const float* Wv    = (const float*)d_in[9];
    const float* Wr    = (const float*)d_in[10];
    const float* Wo    = (const float*)d_in[11];
    const float* mk2   = (const float*)d_in[12];
    const float* mr2   = (const float*)d_in[13];
    const float* Wk2   = (const float*)d_in[14];
    const float* Wv2   = (const float*)d_in[15];
    const float* Wr2   = (const float*)d_in[16];
    float* out = (float*)d_out;

#define SYM(p, s) void* p##_; cudaGetSymbolAddress(&p##_, s); auto* p = (decltype(&s[0]))p##_
    SYM(ek,  g_ek); SYM(v,   g_v);  SYM(r,   g_r);
    SYM(x1,  g_x1); SYM(r2,  g_r2); SYM(sA,  g_sA); SYM(sB,  g_sB);
    SYM(xkh, a_xk_h); SYM(xvh, a_xv_h); SYM(xrh, a_xr_h);
    SYM(rwh, a_rw_h); SYM(k2h, a_k2_h);
    SYM(wkh, w_k_h);  SYM(wvh, w_v_h);  SYM(wrh, w_r_h);  SYM(woh, w_o_h);
    SYM(wr2h, w_r2_h); SYM(wk2h, w_k2_h); SYM(wv2h, w_v2_h);
#undef SYM

    cudaFuncSetAttribute(hgemm_kvr,    cudaFuncAttributeMaxDynamicSharedMemorySize, GSMEM);
    cudaFuncSetAttribute(hgemm_add,    cudaFuncAttributeMaxDynamicSharedMemorySize, GSMEM);
    cudaFuncSetAttribute(hgemm_k2r2,   cudaFuncAttributeMaxDynamicSharedMemorySize, GSMEM);
    cudaFuncSetAttribute(hgemm_muladd, cudaFuncAttributeMaxDynamicSharedMemorySize, GSMEM);

    const dim3 tb(32, 8);
    wsplit5_kernel<<<dim3(Cv/32, Cv/32, 5), tb>>>(Wk, Wv, Wr, Wo, Wr2,
                                                  wkh, wvh, wrh, woh, wr2h);
    wsplit_kernel<<<dim3(Iv/32, Cv/32), tb>>>(Wk2, wk2h, Cv, Iv);  // [C,I] -> [I,C]
    wsplit_kernel<<<dim3(Cv/32, Iv/32), tb>>>(Wv2, wv2h, Iv, Cv);  // [I,C] -> [C,I]

    // --- time mixing ---
    fusedmix3_kernel<<<Mv, 256>>>(x, ln1_w, mk, mv, mr, xkh, xvh, xrh);
    hgemm_kvr<<<dim3(24, 128), 256, GSMEM>>>(xkh, xvh, xrh, wkh, wvh, wrh, ek, v, r);
    wkv_pass1<<<dim3(NCHUNK, Bv), Cv>>>(ek, v, td, sA, sB);
    wkv_pass2<<<Bv, Cv>>>(td, sA, sB);
    wkv_pass3<<<dim3(NCHUNK, Bv), Cv>>>(ek, v, r, td, tf, sA, sB, rwh);
    hgemm_add<<<dim3(8, 128), 256, GSMEM>>>(rwh, woh, x1, x);

    // --- channel mixing ---
    fusedmix2_kernel<<<Mv, 256>>>(x1, ln2_w, mk2, mr2, xkh, xrh);
    hgemm_k2r2<<<dim3(40, 128), 256, GSMEM>>>(xkh, xrh, wk2h, wr2h, k2h, r2);
    hgemm_muladd<<<dim3(8, 128), 256, GSMEM>>>(k2h, wv2h, out, x1, r2);
}